// round 1
// baseline (speedup 1.0000x reference)
#include <cuda_runtime.h>
#include <math.h>

#define BB 4
#define NN 2048
#define DD 512
#define HH 8
#define EE 4
#define RD 2048
#define MROWS (BB*NN)

// ---------------- scratch (device globals: no runtime allocation) ----------------
__device__ float g_probs[MROWS*EE];
__device__ int   g_assigned[MROWS];
__device__ float g_rp[MROWS];
__device__ int   g_dtok[MROWS];
__device__ float g_h[MROWS*DD];
__device__ float g_q[MROWS*DD];
__device__ float g_k[MROWS*DD];
__device__ float g_v[MROWS*DD];
__device__ float g_o[MROWS*DD];
__device__ float g_z[MROWS*DD];
__device__ float g_hm[MROWS*DD];
__device__ float g_hid[(size_t)MROWS*RD];

// ---------------- router: logits + softmax ----------------
__global__ void router_kernel(const float* __restrict__ x,
                              const float* __restrict__ rw,
                              const float* __restrict__ rb) {
    int gw = (blockIdx.x * blockDim.x + threadIdx.x) >> 5;
    int lane = threadIdx.x & 31;
    if (gw >= MROWS) return;
    const float* xr = x + (size_t)gw * DD;
    float a0=0.f,a1=0.f,a2=0.f,a3=0.f;
    for (int k = lane; k < DD; k += 32) {
        float xv = xr[k];
        const float* w = rw + (size_t)k*EE;
        a0 += xv*w[0]; a1 += xv*w[1]; a2 += xv*w[2]; a3 += xv*w[3];
    }
    for (int o = 16; o; o >>= 1) {
        a0 += __shfl_xor_sync(0xffffffffu, a0, o);
        a1 += __shfl_xor_sync(0xffffffffu, a1, o);
        a2 += __shfl_xor_sync(0xffffffffu, a2, o);
        a3 += __shfl_xor_sync(0xffffffffu, a3, o);
    }
    if (lane == 0) {
        float l0=a0+rb[0], l1=a1+rb[1], l2=a2+rb[2], l3=a3+rb[3];
        float mx = fmaxf(fmaxf(l0,l1), fmaxf(l2,l3));
        float e0=expf(l0-mx), e1=expf(l1-mx), e2=expf(l2-mx), e3=expf(l3-mx);
        float inv = 1.f/(e0+e1+e2+e3);
        float* p = g_probs + (size_t)gw*EE;
        p[0]=e0*inv; p[1]=e1*inv; p[2]=e2*inv; p[3]=e3*inv;
    }
}

// ---------------- expert-preferred greedy assignment (bitonic top-k) ----------------
__global__ void assign_kernel() {
    __shared__ unsigned long long keys[NN];
    __shared__ int asg[NN];
    int b = blockIdx.x;
    int t = threadIdx.x;           // 1024 threads
    for (int i = t; i < NN; i += 1024) asg[i] = -1;
    const int caps[EE] = {1024, 512, 256, 256};
    for (int e = EE-1; e >= 1; e--) {
        __syncthreads();
        // key: [unassigned(1) | prob-bits(32) | (2047-idx)(16)]  -> descending sort
        for (int i = t; i < NN; i += 1024) {
            unsigned pb = __float_as_uint(g_probs[((size_t)b*NN+i)*EE + e]); // probs > 0, bits monotone
            unsigned long long key =
                ((unsigned long long)(asg[i] < 0 ? 1u : 0u) << 63) |
                ((unsigned long long)pb << 16) |
                (unsigned long long)(NN-1-i);
            keys[i] = key;
        }
        __syncthreads();
        for (int k = 2; k <= NN; k <<= 1) {
            for (int j = k >> 1; j > 0; j >>= 1) {
                for (int ii = t; ii < NN; ii += 1024) {
                    int l = ii ^ j;
                    if (l > ii) {
                        unsigned long long va = keys[ii], vb = keys[l];
                        bool desc = ((ii & k) == 0);
                        if (desc ? (va < vb) : (va > vb)) { keys[ii]=vb; keys[l]=va; }
                    }
                }
                __syncthreads();
            }
        }
        int cap = caps[e];
        for (int i = t; i < cap; i += 1024) {
            int idx = NN-1 - (int)(keys[i] & 0xffffu);
            asg[idx] = e;
        }
    }
    __syncthreads();
    for (int i = t; i < NN; i += 1024) {
        int a = asg[i]; if (a < 0) a = 0;
        g_assigned[b*NN+i] = a;
        g_rp[b*NN+i] = g_probs[((size_t)b*NN+i)*EE + a];
        g_dtok[b*NN+i] = 64 << a;   // NEST = {64,128,256,512}
    }
}

// ---------------- layernorm + feature mask ----------------
template<int LM>
__global__ void ln_mask_kernel(const float* __restrict__ xin,
                               const float* __restrict__ g,
                               const float* __restrict__ be) {
    int tok = blockIdx.x;
    int t = threadIdx.x;  // 128
    const float* in = (LM == 0) ? xin : g_z;
    float* out = (LM == 0) ? g_h : g_hm;
    const float* xr = in + (size_t)tok * DD;
    float v[4]; float s = 0.f;
    #pragma unroll
    for (int i = 0; i < 4; i++) { v[i] = xr[t + 128*i]; s += v[i]; }
    __shared__ float red[4];
    for (int o = 16; o; o >>= 1) s += __shfl_xor_sync(0xffffffffu, s, o);
    if ((t & 31) == 0) red[t >> 5] = s;
    __syncthreads();
    float mu = (red[0]+red[1]+red[2]+red[3]) * (1.f/DD);
    float s2 = 0.f;
    #pragma unroll
    for (int i = 0; i < 4; i++) { float d = v[i]-mu; s2 += d*d; }
    __syncthreads();
    for (int o = 16; o; o >>= 1) s2 += __shfl_xor_sync(0xffffffffu, s2, o);
    if ((t & 31) == 0) red[t >> 5] = s2;
    __syncthreads();
    float var = (red[0]+red[1]+red[2]+red[3]) * (1.f/DD);
    float rs = rsqrtf(var + 1e-5f);
    int dt = g_dtok[tok];
    float* orow = out + (size_t)tok * DD;
    #pragma unroll
    for (int i = 0; i < 4; i++) {
        int c = t + 128*i;
        orow[c] = (c < dt) ? ((v[i]-mu)*rs*g[c] + be[c]) : 0.f;
    }
}

__device__ __forceinline__ float gelu_f(float x) {
    float x3 = x*x*x;
    return 0.5f * x * (1.f + tanhf(0.7978845608028654f * (x + 0.044715f * x3)));
}

// ---------------- generic tiled SGEMM 64x64x16, fused epilogues ----------------
// MODE 0: qkv = g_h @ wqkv, mask, scatter to g_q/g_k/g_v [B,H,N,64]
// MODE 1: g_z = x + ((g_o @ wo) + bo) * mask
// MODE 2: g_hid = gelu(((g_hm @ w1) + b1f) * mask4)
// MODE 3: out = g_z + (alpha*rp + 1) * (((g_hid @ w2) + b2f) * mask)
template<int MODE>
__global__ void gemm_kernel(const float* __restrict__ Bm,
                            const float* __restrict__ bias,
                            const float* __restrict__ xin,
                            const float* __restrict__ alpha,
                            float* __restrict__ dout) {
    constexpr int KT = (MODE == 3) ? 2048 : 512;
    constexpr int NC = (MODE == 0) ? 1536 : (MODE == 2) ? 2048 : 512;
    const float* A = (MODE == 0) ? g_h : (MODE == 1) ? g_o : (MODE == 2) ? g_hm : g_hid;
    __shared__ float As[16][64];   // k-major
    __shared__ float Bs[16][64];
    int tid = threadIdx.x;          // 256
    int tx = tid & 15, ty = tid >> 4;
    int m0 = blockIdx.y * 64;
    int n0 = blockIdx.x * 64;
    float acc[4][4] = {};
    int arow = tid >> 2;
    int acol = (tid & 3) * 4;
    int brow = tid >> 4;
    int bcol = (tid & 15) * 4;
    for (int k0 = 0; k0 < KT; k0 += 16) {
        float4 av = *(const float4*)&A[(size_t)(m0+arow)*KT + k0 + acol];
        float4 bv = *(const float4*)&Bm[(size_t)(k0+brow)*NC + n0 + bcol];
        __syncthreads();
        As[acol+0][arow] = av.x;
        As[acol+1][arow] = av.y;
        As[acol+2][arow] = av.z;
        As[acol+3][arow] = av.w;
        *(float4*)&Bs[brow][bcol] = bv;
        __syncthreads();
        #pragma unroll
        for (int kk = 0; kk < 16; kk++) {
            float4 a = *(float4*)&As[kk][ty*4];
            float4 bq = *(float4*)&Bs[kk][tx*4];
            float ar[4] = {a.x,a.y,a.z,a.w};
            float br[4] = {bq.x,bq.y,bq.z,bq.w};
            #pragma unroll
            for (int i2=0;i2<4;i2++)
                #pragma unroll
                for (int j2=0;j2<4;j2++)
                    acc[i2][j2] += ar[i2]*br[j2];
        }
    }
    #pragma unroll
    for (int i = 0; i < 4; i++) {
        int row = m0 + ty*4 + i;
        int dt = g_dtok[row];
        #pragma unroll
        for (int j = 0; j < 4; j++) {
            int c = n0 + tx*4 + j;
            float v = acc[i][j];
            if constexpr (MODE == 0) {
                int cc = c & 511;
                v = (cc < dt) ? v : 0.f;
                int sel = c >> 9;
                int hh = cc >> 6, dd = cc & 63;
                int bidx = row >> 11, n = row & (NN-1);
                float* dst = (sel==0) ? g_q : (sel==1) ? g_k : g_v;
                dst[(((size_t)(bidx*HH+hh))*NN + n)*64 + dd] = v;
            } else if constexpr (MODE == 1) {
                v += bias[c];
                v = (c < dt) ? v : 0.f;
                g_z[(size_t)row*DD + c] = xin[(size_t)row*DD + c] + v;
            } else if constexpr (MODE == 2) {
                v += bias[c];
                v = (c < 4*dt) ? v : 0.f;
                g_hid[(size_t)row*RD + c] = gelu_f(v);
            } else {
                v += bias[c];
                v = (c < dt) ? v : 0.f;
                float gate = alpha[0] * g_rp[row] + 1.f;
                dout[(size_t)row*DD + c] = g_z[(size_t)row*DD + c] + gate * v;
            }
        }
    }
}

// ---------------- flash attention fp32 (per (b,h), 64-row blocks) ----------------
__global__ void attn_kernel() {
    extern __shared__ float sm[];
    float* Qs = sm;                      // [64][64] kk-major: Qs[kk*64+r]
    float* Ks = sm + 4096;               // [64][64] kk-major: Ks[kk*64+c]
    float* Vs = sm + 8192;               // [64][68]: Vs[c*68+d]
    float* Ps = sm + 8192 + 64*68;       // [64][65]: Ps[r*65+c]
    int bh = blockIdx.y;
    int b = bh >> 3;
    int h = bh & 7;
    int m0 = blockIdx.x * 64;
    int tid = threadIdx.x;               // 256
    int tx = tid & 15, ty = tid >> 4;
    const float* qb = g_q + (size_t)bh * NN * 64;
    const float* kb = g_k + (size_t)bh * NN * 64;
    const float* vb = g_v + (size_t)bh * NN * 64;
    {
        int r = tid & 63;
        int kk4 = (tid >> 6) * 16;
        #pragma unroll
        for (int i = 0; i < 4; i++) {
            float4 qv = *(const float4*)&qb[(size_t)(m0+r)*64 + kk4 + i*4];
            Qs[(kk4+i*4+0)*64 + r] = qv.x;
            Qs[(kk4+i*4+1)*64 + r] = qv.y;
            Qs[(kk4+i*4+2)*64 + r] = qv.z;
            Qs[(kk4+i*4+3)*64 + r] = qv.w;
        }
    }
    float mold[4], lsum[4], O[4][4];
    #pragma unroll
    for (int i=0;i<4;i++){ mold[i] = -1e30f; lsum[i]=0.f;
        #pragma unroll
        for (int j=0;j<4;j++) O[i][j]=0.f; }
    __syncthreads();
    for (int n0 = 0; n0 < NN; n0 += 64) {
        {
            int c = tid & 63;
            int kk4 = (tid >> 6) * 16;
            #pragma unroll
            for (int i = 0; i < 4; i++) {
                float4 kv = *(const float4*)&kb[(size_t)(n0+c)*64 + kk4 + i*4];
                Ks[(kk4+i*4+0)*64 + c] = kv.x;
                Ks[(kk4+i*4+1)*64 + c] = kv.y;
                Ks[(kk4+i*4+2)*64 + c] = kv.z;
                Ks[(kk4+i*4+3)*64 + c] = kv.w;
                float4 vv = *(const float4*)&vb[(size_t)(n0+c)*64 + kk4 + i*4];
                *(float4*)&Vs[c*68 + kk4 + i*4] = vv;
            }
        }
        __syncthreads();
        float S[4][4] = {};
        #pragma unroll 16
        for (int kk = 0; kk < 64; kk++) {
            float4 a  = *(float4*)&Qs[kk*64 + ty*4];
            float4 bk = *(float4*)&Ks[kk*64 + tx*4];
            float ar[4] = {a.x,a.y,a.z,a.w};
            float br[4] = {bk.x,bk.y,bk.z,bk.w};
            #pragma unroll
            for (int i2=0;i2<4;i2++)
                #pragma unroll
                for (int j2=0;j2<4;j2++)
                    S[i2][j2] += ar[i2]*br[j2];
        }
        #pragma unroll
        for (int i = 0; i < 4; i++) {
            #pragma unroll
            for (int j = 0; j < 4; j++) S[i][j] *= 0.125f;  // 1/sqrt(64)
            float mx = fmaxf(fmaxf(S[i][0],S[i][1]), fmaxf(S[i][2],S[i][3]));
            for (int o = 8; o; o >>= 1) mx = fmaxf(mx, __shfl_xor_sync(0xffffffffu, mx, o));
            float mn = fmaxf(mold[i], mx);
            float corr = __expf(mold[i] - mn);
            float rs = 0.f;
            #pragma unroll
            for (int j = 0; j < 4; j++) { float p = __expf(S[i][j]-mn); S[i][j]=p; rs += p; }
            for (int o = 8; o; o >>= 1) rs += __shfl_xor_sync(0xffffffffu, rs, o);
            lsum[i] = lsum[i]*corr + rs;
            #pragma unroll
            for (int j = 0; j < 4; j++) O[i][j] *= corr;
            mold[i] = mn;
        }
        #pragma unroll
        for (int i=0;i<4;i++)
            #pragma unroll
            for (int j=0;j<4;j++)
                Ps[(ty*4+i)*65 + tx*4+j] = S[i][j];
        __syncthreads();
        #pragma unroll 16
        for (int c = 0; c < 64; c++) {
            float4 vv = *(float4*)&Vs[c*68 + tx*4];
            float pr[4];
            #pragma unroll
            for (int i=0;i<4;i++) pr[i] = Ps[(ty*4+i)*65 + c];
            float vr[4] = {vv.x,vv.y,vv.z,vv.w};
            #pragma unroll
            for (int i2=0;i2<4;i2++)
                #pragma unroll
                for (int j2=0;j2<4;j2++)
                    O[i2][j2] += pr[i2]*vr[j2];
        }
        __syncthreads();
    }
    #pragma unroll
    for (int i = 0; i < 4; i++) {
        int n = m0 + ty*4 + i;
        int row = b*NN + n;
        int dt = g_dtok[row];
        float inv = 1.f / lsum[i];
        #pragma unroll
        for (int j = 0; j < 4; j++) {
            int feat = h*64 + tx*4 + j;
            g_o[(size_t)row*DD + feat] = (feat < dt) ? O[i][j]*inv : 0.f;
        }
    }
}

// optional extra outputs (assigned, rp) if harness expects the full tuple
__global__ void extras_kernel(float* dout, int out_size) {
    int i = blockIdx.x * blockDim.x + threadIdx.x;
    if (i >= MROWS) return;
    const int base = MROWS*DD;
    if (out_size >= base + MROWS)   dout[base + i] = (float)g_assigned[i];
    if (out_size >= base + 2*MROWS) dout[base + MROWS + i] = g_rp[i];
}

extern "C" void kernel_launch(void* const* d_in, const int* in_sizes, int n_in,
                              void* d_out, int out_size) {
    const float* x    = (const float*)d_in[0];
    const float* r_w  = (const float*)d_in[1];
    const float* r_b  = (const float*)d_in[2];
    const float* g1   = (const float*)d_in[3];
    const float* b1   = (const float*)d_in[4];
    const float* g2   = (const float*)d_in[5];
    const float* b2   = (const float*)d_in[6];
    const float* wqkv = (const float*)d_in[7];
    const float* wo   = (const float*)d_in[8];
    const float* bo   = (const float*)d_in[9];
    const float* w1   = (const float*)d_in[10];
    const float* b1f  = (const float*)d_in[11];
    const float* w2   = (const float*)d_in[12];
    const float* b2f  = (const float*)d_in[13];
    const float* alpha= (const float*)d_in[14];
    float* out = (float*)d_out;

    router_kernel<<<MROWS/4, 128>>>(x, r_w, r_b);
    assign_kernel<<<BB, 1024>>>();
    ln_mask_kernel<0><<<MROWS, 128>>>(x, g1, b1);
    gemm_kernel<0><<<dim3(1536/64, MROWS/64), 256>>>(wqkv, nullptr, nullptr, nullptr, nullptr);
    constexpr int attn_smem = (4096*2 + 64*68 + 64*65) * 4;  // 66816 B
    cudaFuncSetAttribute(attn_kernel, cudaFuncAttributeMaxDynamicSharedMemorySize, attn_smem);
    attn_kernel<<<dim3(NN/64, BB*HH), 256, attn_smem>>>();
    gemm_kernel<1><<<dim3(512/64, MROWS/64), 256>>>(wo, bo, x, nullptr, nullptr);
    ln_mask_kernel<1><<<MROWS, 128>>>(nullptr, g2, b2);
    gemm_kernel<2><<<dim3(2048/64, MROWS/64), 256>>>(w1, b1f, nullptr, nullptr, nullptr);
    gemm_kernel<3><<<dim3(512/64, MROWS/64), 256>>>(w2, b2f, nullptr, alpha, out);
    if (out_size > MROWS*DD)
        extras_kernel<<<(MROWS+255)/256, 256>>>(out, out_size);
}

// round 3
// speedup vs baseline: 1.2314x; 1.2314x over previous
#include <cuda_runtime.h>
#include <math.h>

#define BB 4
#define NN 2048
#define DD 512
#define HH 8
#define EE 4
#define RD 2048
#define MROWS (BB*NN)

// ---------------- scratch (device globals: no runtime allocation) ----------------
__device__ float g_probs[MROWS*EE];
__device__ int   g_assigned[MROWS];
__device__ float g_rp[MROWS];
__device__ int   g_dtok[MROWS];
__device__ float g_h[MROWS*DD];
__device__ float g_q[MROWS*DD];
__device__ float g_k[MROWS*DD];
__device__ float g_v[MROWS*DD];
__device__ float g_o[MROWS*DD];
__device__ float g_z[MROWS*DD];
__device__ float g_hm[MROWS*DD];
__device__ float g_hid[(size_t)MROWS*RD];

// ---------------- router: logits + softmax ----------------
__global__ void router_kernel(const float* __restrict__ x,
                              const float* __restrict__ rw,
                              const float* __restrict__ rb) {
    int gw = (blockIdx.x * blockDim.x + threadIdx.x) >> 5;
    int lane = threadIdx.x & 31;
    if (gw >= MROWS) return;
    const float* xr = x + (size_t)gw * DD;
    float a0=0.f,a1=0.f,a2=0.f,a3=0.f;
    for (int k = lane; k < DD; k += 32) {
        float xv = xr[k];
        const float* w = rw + (size_t)k*EE;
        a0 += xv*w[0]; a1 += xv*w[1]; a2 += xv*w[2]; a3 += xv*w[3];
    }
    for (int o = 16; o; o >>= 1) {
        a0 += __shfl_xor_sync(0xffffffffu, a0, o);
        a1 += __shfl_xor_sync(0xffffffffu, a1, o);
        a2 += __shfl_xor_sync(0xffffffffu, a2, o);
        a3 += __shfl_xor_sync(0xffffffffu, a3, o);
    }
    if (lane == 0) {
        float l0=a0+rb[0], l1=a1+rb[1], l2=a2+rb[2], l3=a3+rb[3];
        float mx = fmaxf(fmaxf(l0,l1), fmaxf(l2,l3));
        float e0=expf(l0-mx), e1=expf(l1-mx), e2=expf(l2-mx), e3=expf(l3-mx);
        float inv = 1.f/(e0+e1+e2+e3);
        float* p = g_probs + (size_t)gw*EE;
        p[0]=e0*inv; p[1]=e1*inv; p[2]=e2*inv; p[3]=e3*inv;
    }
}

// ---------------- expert-preferred greedy assignment (bitonic top-k) ----------------
__global__ void assign_kernel() {
    __shared__ unsigned long long keys[NN];
    __shared__ int asg[NN];
    int b = blockIdx.x;
    int t = threadIdx.x;           // 1024 threads
    for (int i = t; i < NN; i += 1024) asg[i] = -1;
    const int caps[EE] = {1024, 512, 256, 256};
    for (int e = EE-1; e >= 1; e--) {
        __syncthreads();
        for (int i = t; i < NN; i += 1024) {
            unsigned pb = __float_as_uint(g_probs[((size_t)b*NN+i)*EE + e]);
            unsigned long long key =
                ((unsigned long long)(asg[i] < 0 ? 1u : 0u) << 63) |
                ((unsigned long long)pb << 16) |
                (unsigned long long)(NN-1-i);
            keys[i] = key;
        }
        __syncthreads();
        for (int k = 2; k <= NN; k <<= 1) {
            for (int j = k >> 1; j > 0; j >>= 1) {
                for (int ii = t; ii < NN; ii += 1024) {
                    int l = ii ^ j;
                    if (l > ii) {
                        unsigned long long va = keys[ii], vb = keys[l];
                        bool desc = ((ii & k) == 0);
                        if (desc ? (va < vb) : (va > vb)) { keys[ii]=vb; keys[l]=va; }
                    }
                }
                __syncthreads();
            }
        }
        int cap = caps[e];
        for (int i = t; i < cap; i += 1024) {
            int idx = NN-1 - (int)(keys[i] & 0xffffu);
            asg[idx] = e;
        }
    }
    __syncthreads();
    for (int i = t; i < NN; i += 1024) {
        int a = asg[i]; if (a < 0) a = 0;
        g_assigned[b*NN+i] = a;
        g_rp[b*NN+i] = g_probs[((size_t)b*NN+i)*EE + a];
        g_dtok[b*NN+i] = 64 << a;
    }
}

// ---------------- layernorm + feature mask ----------------
template<int LM>
__global__ void ln_mask_kernel(const float* __restrict__ xin,
                               const float* __restrict__ g,
                               const float* __restrict__ be) {
    int tok = blockIdx.x;
    int t = threadIdx.x;  // 128
    const float* in = (LM == 0) ? xin : g_z;
    float* out = (LM == 0) ? g_h : g_hm;
    const float* xr = in + (size_t)tok * DD;
    float v[4]; float s = 0.f;
    #pragma unroll
    for (int i = 0; i < 4; i++) { v[i] = xr[t + 128*i]; s += v[i]; }
    __shared__ float red[4];
    for (int o = 16; o; o >>= 1) s += __shfl_xor_sync(0xffffffffu, s, o);
    if ((t & 31) == 0) red[t >> 5] = s;
    __syncthreads();
    float mu = (red[0]+red[1]+red[2]+red[3]) * (1.f/DD);
    float s2 = 0.f;
    #pragma unroll
    for (int i = 0; i < 4; i++) { float d = v[i]-mu; s2 += d*d; }
    __syncthreads();
    for (int o = 16; o; o >>= 1) s2 += __shfl_xor_sync(0xffffffffu, s2, o);
    if ((t & 31) == 0) red[t >> 5] = s2;
    __syncthreads();
    float var = (red[0]+red[1]+red[2]+red[3]) * (1.f/DD);
    float rs = rsqrtf(var + 1e-5f);
    int dt = g_dtok[tok];
    float* orow = out + (size_t)tok * DD;
    #pragma unroll
    for (int i = 0; i < 4; i++) {
        int c = t + 128*i;
        orow[c] = (c < dt) ? ((v[i]-mu)*rs*g[c] + be[c]) : 0.f;
    }
}

__device__ __forceinline__ float gelu_f(float x) {
    float x3 = x*x*x;
    return 0.5f * x * (1.f + tanhf(0.7978845608028654f * (x + 0.044715f * x3)));
}

// ---------------- tiled SGEMM 128x128x8, 8x8 microtile, fused epilogues ----------------
template<int MODE>
__global__ __launch_bounds__(256)
void gemm_kernel(const float* __restrict__ Bm,
                 const float* __restrict__ bias,
                 const float* __restrict__ xin,
                 const float* __restrict__ alpha,
                 float* __restrict__ dout) {
    constexpr int KT = (MODE == 3) ? 2048 : 512;
    constexpr int NC = (MODE == 0) ? 1536 : (MODE == 2) ? 2048 : 512;
    const float* A = (MODE == 0) ? g_h : (MODE == 1) ? g_o : (MODE == 2) ? g_hm : g_hid;
    __shared__ float As[8][128];   // k-major
    __shared__ float Bs[8][128];
    int tid = threadIdx.x;          // 256
    int tx = tid & 15, ty = tid >> 4;
    int m0 = blockIdx.y * 128;
    int n0 = blockIdx.x * 128;
    float acc[8][8] = {};
    int arow = tid & 127;               // A tile row
    int acolg = (tid >> 7) * 4;         // A tile k offset (0 or 4)
    int brow = tid >> 5;                // B tile k row (0..7)
    int bcol = (tid & 31) * 4;          // B tile col

    const float* Aptr = A + (size_t)(m0 + arow) * KT + acolg;
    const float* Bptr = Bm + (size_t)brow * NC + n0 + bcol;

    float4 aReg = *(const float4*)Aptr;
    float4 bReg = *(const float4*)Bptr;

    for (int k0 = 0; k0 < KT; k0 += 8) {
        As[acolg+0][arow] = aReg.x;
        As[acolg+1][arow] = aReg.y;
        As[acolg+2][arow] = aReg.z;
        As[acolg+3][arow] = aReg.w;
        *(float4*)&Bs[brow][bcol] = bReg;
        __syncthreads();
        if (k0 + 8 < KT) {
            aReg = *(const float4*)(Aptr + k0 + 8);
            bReg = *(const float4*)(Bptr + (size_t)(k0 + 8) * NC);
        }
        #pragma unroll
        for (int kk = 0; kk < 8; kk++) {
            float4 a0 = *(float4*)&As[kk][ty*4];
            float4 a1 = *(float4*)&As[kk][64 + ty*4];
            float4 b0 = *(float4*)&Bs[kk][tx*4];
            float4 b1 = *(float4*)&Bs[kk][64 + tx*4];
            float ar[8] = {a0.x,a0.y,a0.z,a0.w,a1.x,a1.y,a1.z,a1.w};
            float br[8] = {b0.x,b0.y,b0.z,b0.w,b1.x,b1.y,b1.z,b1.w};
            #pragma unroll
            for (int i2=0;i2<8;i2++)
                #pragma unroll
                for (int j2=0;j2<8;j2++)
                    acc[i2][j2] += ar[i2]*br[j2];
        }
        __syncthreads();
    }
    #pragma unroll
    for (int i = 0; i < 8; i++) {
        int row = m0 + ty*4 + (i & 3) + (i >> 2) * 64;
        int dt = g_dtok[row];
        #pragma unroll
        for (int j = 0; j < 8; j++) {
            int c = n0 + tx*4 + (j & 3) + (j >> 2) * 64;
            float v = acc[i][j];
            if constexpr (MODE == 0) {
                int cc = c & 511;
                v = (cc < dt) ? v : 0.f;
                int sel = c >> 9;
                int hh = cc >> 6, dd = cc & 63;
                int bidx = row >> 11, n = row & (NN-1);
                float* dst = (sel==0) ? g_q : (sel==1) ? g_k : g_v;
                dst[(((size_t)(bidx*HH+hh))*NN + n)*64 + dd] = v;
            } else if constexpr (MODE == 1) {
                v += bias[c];
                v = (c < dt) ? v : 0.f;
                g_z[(size_t)row*DD + c] = xin[(size_t)row*DD + c] + v;
            } else if constexpr (MODE == 2) {
                v += bias[c];
                v = (c < 4*dt) ? v : 0.f;
                g_hid[(size_t)row*RD + c] = gelu_f(v);
            } else {
                v += bias[c];
                v = (c < dt) ? v : 0.f;
                float gate = alpha[0] * g_rp[row] + 1.f;
                dout[(size_t)row*DD + c] = g_z[(size_t)row*DD + c] + gate * v;
            }
        }
    }
}

// ---------------- flash attention fp32: 128 q-rows per CTA, 64-key tiles ----------------
__global__ __launch_bounds__(256)
void attn_kernel() {
    extern __shared__ float sm[];
    float* Qs = sm;                      // [64][128] kk-major
    float* Ks = Qs + 64*128;             // [64][64]  kk-major
    float* Vs = Ks + 64*64;              // [64][68]
    float* Ps = Vs + 64*68;              // [128][68]
    int bh = blockIdx.y;
    int b = bh >> 3;
    int h = bh & 7;
    int m0 = blockIdx.x * 128;
    int tid = threadIdx.x;               // 256
    int tx = tid & 15, ty = tid >> 4;
    const float* qb = g_q + (size_t)bh * NN * 64;
    const float* kb = g_k + (size_t)bh * NN * 64;
    const float* vb = g_v + (size_t)bh * NN * 64;
    {
        int r = tid & 127;
        int kkbase = (tid >> 7) * 32;
        #pragma unroll
        for (int i = 0; i < 8; i++) {
            float4 qv = *(const float4*)&qb[(size_t)(m0+r)*64 + kkbase + i*4];
            Qs[(kkbase+i*4+0)*128 + r] = qv.x;
            Qs[(kkbase+i*4+1)*128 + r] = qv.y;
            Qs[(kkbase+i*4+2)*128 + r] = qv.z;
            Qs[(kkbase+i*4+3)*128 + r] = qv.w;
        }
    }
    float mold[8], lsum[8], O[8][4];
    #pragma unroll
    for (int i=0;i<8;i++){ mold[i] = -1e30f; lsum[i]=0.f;
        #pragma unroll
        for (int j=0;j<4;j++) O[i][j]=0.f; }
    __syncthreads();
    for (int n0 = 0; n0 < NN; n0 += 64) {
        {
            int c = tid & 63;
            int kk4 = (tid >> 6) * 16;
            #pragma unroll
            for (int i = 0; i < 4; i++) {
                float4 kv = *(const float4*)&kb[(size_t)(n0+c)*64 + kk4 + i*4];
                Ks[(kk4+i*4+0)*64 + c] = kv.x;
                Ks[(kk4+i*4+1)*64 + c] = kv.y;
                Ks[(kk4+i*4+2)*64 + c] = kv.z;
                Ks[(kk4+i*4+3)*64 + c] = kv.w;
                float4 vv = *(const float4*)&vb[(size_t)(n0+c)*64 + kk4 + i*4];
                *(float4*)&Vs[c*68 + kk4 + i*4] = vv;
            }
        }
        __syncthreads();
        float S[8][4] = {};
        #pragma unroll 8
        for (int kk = 0; kk < 64; kk++) {
            float4 a0 = *(float4*)&Qs[kk*128 + ty*4];
            float4 a1 = *(float4*)&Qs[kk*128 + 64 + ty*4];
            float4 bk = *(float4*)&Ks[kk*64 + tx*4];
            float ar[8] = {a0.x,a0.y,a0.z,a0.w,a1.x,a1.y,a1.z,a1.w};
            float br[4] = {bk.x,bk.y,bk.z,bk.w};
            #pragma unroll
            for (int i2=0;i2<8;i2++)
                #pragma unroll
                for (int j2=0;j2<4;j2++)
                    S[i2][j2] += ar[i2]*br[j2];
        }
        #pragma unroll
        for (int i = 0; i < 8; i++) {
            #pragma unroll
            for (int j = 0; j < 4; j++) S[i][j] *= 0.125f;  // 1/sqrt(64)
            float mx = fmaxf(fmaxf(S[i][0],S[i][1]), fmaxf(S[i][2],S[i][3]));
            for (int o = 8; o; o >>= 1) mx = fmaxf(mx, __shfl_xor_sync(0xffffffffu, mx, o));
            float mn = fmaxf(mold[i], mx);
            float corr = __expf(mold[i] - mn);
            float rs = 0.f;
            #pragma unroll
            for (int j = 0; j < 4; j++) { float p = __expf(S[i][j]-mn); S[i][j]=p; rs += p; }
            for (int o = 8; o; o >>= 1) rs += __shfl_xor_sync(0xffffffffu, rs, o);
            lsum[i] = lsum[i]*corr + rs;
            #pragma unroll
            for (int j = 0; j < 4; j++) O[i][j] *= corr;
            mold[i] = mn;
        }
        #pragma unroll
        for (int i=0;i<8;i++) {
            int ri = ty*4 + (i & 3) + (i >> 2) * 64;
            #pragma unroll
            for (int j=0;j<4;j++)
                Ps[ri*68 + tx*4+j] = S[i][j];
        }
        __syncthreads();
        #pragma unroll 8
        for (int c = 0; c < 64; c++) {
            float4 vv = *(float4*)&Vs[c*68 + tx*4];
            float pr[8];
            #pragma unroll
            for (int i=0;i<8;i++) {
                int ri = ty*4 + (i & 3) + (i >> 2) * 64;
                pr[i] = Ps[ri*68 + c];
            }
            float vr[4] = {vv.x,vv.y,vv.z,vv.w};
            #pragma unroll
            for (int i2=0;i2<8;i2++)
                #pragma unroll
                for (int j2=0;j2<4;j2++)
                    O[i2][j2] += pr[i2]*vr[j2];
        }
        __syncthreads();
    }
    #pragma unroll
    for (int i = 0; i < 8; i++) {
        int ri = ty*4 + (i & 3) + (i >> 2) * 64;
        int n = m0 + ri;
        int row = b*NN + n;
        int dt = g_dtok[row];
        float inv = 1.f / lsum[i];
        #pragma unroll
        for (int j = 0; j < 4; j++) {
            int feat = h*64 + tx*4 + j;
            g_o[(size_t)row*DD + feat] = (feat < dt) ? O[i][j]*inv : 0.f;
        }
    }
}

// extra outputs (assigned, rp) — reference returns the full tuple
__global__ void extras_kernel(float* dout, int out_size) {
    int i = blockIdx.x * blockDim.x + threadIdx.x;
    if (i >= MROWS) return;
    const int base = MROWS*DD;
    if (out_size >= base + MROWS)   dout[base + i] = (float)g_assigned[i];
    if (out_size >= base + 2*MROWS) dout[base + MROWS + i] = g_rp[i];
}

extern "C" void kernel_launch(void* const* d_in, const int* in_sizes, int n_in,
                              void* d_out, int out_size) {
    const float* x    = (const float*)d_in[0];
    const float* r_w  = (const float*)d_in[1];
    const float* r_b  = (const float*)d_in[2];
    const float* g1   = (const float*)d_in[3];
    const float* b1   = (const float*)d_in[4];
    const float* g2   = (const float*)d_in[5];
    const float* b2   = (const float*)d_in[6];
    const float* wqkv = (const float*)d_in[7];
    const float* wo   = (const float*)d_in[8];
    const float* bo   = (const float*)d_in[9];
    const float* w1   = (const float*)d_in[10];
    const float* b1f  = (const float*)d_in[11];
    const float* w2   = (const float*)d_in[12];
    const float* b2f  = (const float*)d_in[13];
    const float* alpha= (const float*)d_in[14];
    float* out = (float*)d_out;

    router_kernel<<<MROWS/4, 128>>>(x, r_w, r_b);
    assign_kernel<<<BB, 1024>>>();
    ln_mask_kernel<0><<<MROWS, 128>>>(x, g1, b1);
    gemm_kernel<0><<<dim3(1536/128, MROWS/128), 256>>>(wqkv, nullptr, nullptr, nullptr, nullptr);
    constexpr int attn_smem = (64*128 + 64*64 + 64*68 + 128*68) * 4;  // 101376 B
    cudaFuncSetAttribute(attn_kernel, cudaFuncAttributeMaxDynamicSharedMemorySize, attn_smem);
    attn_kernel<<<dim3(NN/128, BB*HH), 256, attn_smem>>>();
    gemm_kernel<1><<<dim3(512/128, MROWS/128), 256>>>(wo, bo, x, nullptr, nullptr);
    ln_mask_kernel<1><<<MROWS, 128>>>(nullptr, g2, b2);
    gemm_kernel<2><<<dim3(2048/128, MROWS/128), 256>>>(w1, b1f, nullptr, nullptr, nullptr);
    gemm_kernel<3><<<dim3(512/128, MROWS/128), 256>>>(w2, b2f, nullptr, alpha, out);
    if (out_size > MROWS*DD)
        extras_kernel<<<(MROWS+255)/256, 256>>>(out, out_size);
}

// round 7
// speedup vs baseline: 1.5575x; 1.2648x over previous
#include <cuda_runtime.h>
#include <cuda_bf16.h>
#include <math.h>
#include <stdint.h>

#define BB 4
#define NN 2048
#define DD 512
#define HH 8
#define EE 4
#define RD 2048
#define MROWS (BB*NN)

// ---------------- scratch (device globals: no runtime allocation) ----------------
__device__ float g_probs[MROWS*EE];
__device__ int   g_assigned[MROWS];
__device__ float g_rp[MROWS];
__device__ int   g_dtok[MROWS];
__device__ float g_q[MROWS*DD];
__device__ float g_k[MROWS*DD];
__device__ float g_v[MROWS*DD];
__device__ float g_z[MROWS*DD];
// split-bf16 activations (hi/lo)
__device__ __nv_bfloat16 g_h_h[MROWS*DD],  g_h_l[MROWS*DD];
__device__ __nv_bfloat16 g_o_h[MROWS*DD],  g_o_l[MROWS*DD];
__device__ __nv_bfloat16 g_hm_h[MROWS*DD], g_hm_l[MROWS*DD];
__device__ __nv_bfloat16 g_hid_h[(size_t)MROWS*RD], g_hid_l[(size_t)MROWS*RD];
// transposed split-bf16 weights  Wt[n][k]
__device__ __nv_bfloat16 g_wqkvT_h[1536*512], g_wqkvT_l[1536*512];
__device__ __nv_bfloat16 g_woT_h[512*512],    g_woT_l[512*512];
__device__ __nv_bfloat16 g_w1T_h[2048*512],   g_w1T_l[2048*512];
__device__ __nv_bfloat16 g_w2T_h[512*2048],   g_w2T_l[512*2048];

// ---------------- PTX helpers (baseline ISA only: ldmatrix + mma.sync) ----------------
__device__ __forceinline__ uint32_t smem_u32(const void* p) {
    uint32_t a;
    asm("{ .reg .u64 t; cvta.to.shared.u64 t, %1; cvt.u32.u64 %0, t; }" : "=r"(a) : "l"(p));
    return a;
}
__device__ __forceinline__ void ldsm_x4(uint32_t* r, uint32_t addr) {
    asm volatile("ldmatrix.sync.aligned.m8n8.x4.shared.b16 {%0,%1,%2,%3}, [%4];"
                 : "=r"(r[0]), "=r"(r[1]), "=r"(r[2]), "=r"(r[3]) : "r"(addr));
}
__device__ __forceinline__ void ldsm_x2(uint32_t* r, uint32_t addr) {
    asm volatile("ldmatrix.sync.aligned.m8n8.x2.shared.b16 {%0,%1}, [%2];"
                 : "=r"(r[0]), "=r"(r[1]) : "r"(addr));
}
__device__ __forceinline__ void mma16816(float* c, const uint32_t* a, const uint32_t* b) {
    asm volatile(
        "mma.sync.aligned.m16n8k16.row.col.f32.bf16.bf16.f32 "
        "{%0,%1,%2,%3}, {%4,%5,%6,%7}, {%8,%9}, {%0,%1,%2,%3};"
        : "+f"(c[0]), "+f"(c[1]), "+f"(c[2]), "+f"(c[3])
        : "r"(a[0]), "r"(a[1]), "r"(a[2]), "r"(a[3]), "r"(b[0]), "r"(b[1]));
}
__device__ __forceinline__ void bf16_split(float v, __nv_bfloat16& h, __nv_bfloat16& l) {
    h = __float2bfloat16(v);
    l = __float2bfloat16(v - __bfloat162float(h));
}

// ---------------- router: logits + softmax ----------------
__global__ void router_kernel(const float* __restrict__ x,
                              const float* __restrict__ rw,
                              const float* __restrict__ rb) {
    int gw = (blockIdx.x * blockDim.x + threadIdx.x) >> 5;
    int lane = threadIdx.x & 31;
    if (gw >= MROWS) return;
    const float* xr = x + (size_t)gw * DD;
    float a0=0.f,a1=0.f,a2=0.f,a3=0.f;
    for (int k = lane; k < DD; k += 32) {
        float xv = xr[k];
        const float* w = rw + (size_t)k*EE;
        a0 += xv*w[0]; a1 += xv*w[1]; a2 += xv*w[2]; a3 += xv*w[3];
    }
    for (int o = 16; o; o >>= 1) {
        a0 += __shfl_xor_sync(0xffffffffu, a0, o);
        a1 += __shfl_xor_sync(0xffffffffu, a1, o);
        a2 += __shfl_xor_sync(0xffffffffu, a2, o);
        a3 += __shfl_xor_sync(0xffffffffu, a3, o);
    }
    if (lane == 0) {
        float l0=a0+rb[0], l1=a1+rb[1], l2=a2+rb[2], l3=a3+rb[3];
        float mx = fmaxf(fmaxf(l0,l1), fmaxf(l2,l3));
        float e0=expf(l0-mx), e1=expf(l1-mx), e2=expf(l2-mx), e3=expf(l3-mx);
        float inv = 1.f/(e0+e1+e2+e3);
        float* p = g_probs + (size_t)gw*EE;
        p[0]=e0*inv; p[1]=e1*inv; p[2]=e2*inv; p[3]=e3*inv;
    }
}

// ---------------- expert-preferred greedy assignment (bitonic top-k) ----------------
__global__ void assign_kernel() {
    __shared__ unsigned long long keys[NN];
    __shared__ int asg[NN];
    int b = blockIdx.x;
    int t = threadIdx.x;
    for (int i = t; i < NN; i += 1024) asg[i] = -1;
    const int caps[EE] = {1024, 512, 256, 256};
    for (int e = EE-1; e >= 1; e--) {
        __syncthreads();
        for (int i = t; i < NN; i += 1024) {
            unsigned pb = __float_as_uint(g_probs[((size_t)b*NN+i)*EE + e]);
            unsigned long long key =
                ((unsigned long long)(asg[i] < 0 ? 1u : 0u) << 63) |
                ((unsigned long long)pb << 16) |
                (unsigned long long)(NN-1-i);
            keys[i] = key;
        }
        __syncthreads();
        for (int k = 2; k <= NN; k <<= 1) {
            for (int j = k >> 1; j > 0; j >>= 1) {
                for (int ii = t; ii < NN; ii += 1024) {
                    int l = ii ^ j;
                    if (l > ii) {
                        unsigned long long va = keys[ii], vb = keys[l];
                        bool desc = ((ii & k) == 0);
                        if (desc ? (va < vb) : (va > vb)) { keys[ii]=vb; keys[l]=va; }
                    }
                }
                __syncthreads();
            }
        }
        int cap = caps[e];
        for (int i = t; i < cap; i += 1024) {
            int idx = NN-1 - (int)(keys[i] & 0xffffu);
            asg[idx] = e;
        }
    }
    __syncthreads();
    for (int i = t; i < NN; i += 1024) {
        int a = asg[i]; if (a < 0) a = 0;
        g_assigned[b*NN+i] = a;
        g_rp[b*NN+i] = g_probs[((size_t)b*NN+i)*EE + a];
        g_dtok[b*NN+i] = 64 << a;
    }
}

// ---------------- weight transpose + split-bf16 convert: Wt[n][k] = W[k][n] ----------------
template<int MODE>
__global__ void wconv_kernel(const float* __restrict__ W) {
    constexpr int K = (MODE==3)?2048:512;
    constexpr int N = (MODE==0)?1536:(MODE==2)?2048:512;
    __nv_bfloat16* oh = (MODE==0)?g_wqkvT_h:(MODE==1)?g_woT_h:(MODE==2)?g_w1T_h:g_w2T_h;
    __nv_bfloat16* ol = (MODE==0)?g_wqkvT_l:(MODE==1)?g_woT_l:(MODE==2)?g_w1T_l:g_w2T_l;
    __shared__ float tbuf[32][33];
    int n0 = blockIdx.x*32, k0 = blockIdx.y*32;
    int tx = threadIdx.x, ty = threadIdx.y;
    #pragma unroll
    for (int i = 0; i < 4; i++)
        tbuf[ty+i*8][tx] = W[(size_t)(k0+ty+i*8)*N + n0+tx];
    __syncthreads();
    #pragma unroll
    for (int i = 0; i < 4; i++) {
        int n = n0 + ty + i*8, k = k0 + tx;
        float v = tbuf[tx][ty+i*8];
        __nv_bfloat16 h, l; bf16_split(v, h, l);
        oh[(size_t)n*K + k] = h;
        ol[(size_t)n*K + k] = l;
    }
}

// ---------------- layernorm + feature mask -> split bf16 ----------------
template<int LM>
__global__ void ln_mask_kernel(const float* __restrict__ xin,
                               const float* __restrict__ g,
                               const float* __restrict__ be) {
    int tok = blockIdx.x;
    int t = threadIdx.x;  // 128
    const float* in = (LM == 0) ? xin : g_z;
    __nv_bfloat16* oh = (LM == 0) ? g_h_h : g_hm_h;
    __nv_bfloat16* ol = (LM == 0) ? g_h_l : g_hm_l;
    const float* xr = in + (size_t)tok * DD;
    float v[4]; float s = 0.f;
    #pragma unroll
    for (int i = 0; i < 4; i++) { v[i] = xr[t + 128*i]; s += v[i]; }
    __shared__ float red[4];
    for (int o = 16; o; o >>= 1) s += __shfl_xor_sync(0xffffffffu, s, o);
    if ((t & 31) == 0) red[t >> 5] = s;
    __syncthreads();
    float mu = (red[0]+red[1]+red[2]+red[3]) * (1.f/DD);
    float s2 = 0.f;
    #pragma unroll
    for (int i = 0; i < 4; i++) { float d = v[i]-mu; s2 += d*d; }
    __syncthreads();
    for (int o = 16; o; o >>= 1) s2 += __shfl_xor_sync(0xffffffffu, s2, o);
    if ((t & 31) == 0) red[t >> 5] = s2;
    __syncthreads();
    float var = (red[0]+red[1]+red[2]+red[3]) * (1.f/DD);
    float rs = rsqrtf(var + 1e-5f);
    int dt = g_dtok[tok];
    #pragma unroll
    for (int i = 0; i < 4; i++) {
        int c = t + 128*i;
        float val = (c < dt) ? ((v[i]-mu)*rs*g[c] + be[c]) : 0.f;
        __nv_bfloat16 h, l; bf16_split(val, h, l);
        oh[(size_t)tok*DD + c] = h;
        ol[(size_t)tok*DD + c] = l;
    }
}

__device__ __forceinline__ float gelu_f(float x) {
    float x3 = x*x*x;
    return 0.5f * x * (1.f + tanhf(0.7978845608028654f * (x + 0.044715f * x3)));
}

// ---------------- HMMA split-bf16 GEMM: 128x128 CTA tile, 8 warps x (64x32) ----------------
// smem tiles 128x32 bf16, pitch 40 (phase-conflict-free for ldmatrix)
// MODE 0: qkv = h @ wqkv, mask, scatter -> g_q/g_k/g_v fp32 [B,H,N,64]
// MODE 1: g_z = x + ((o @ wo) + bo) * mask
// MODE 2: hid = gelu(((hm @ w1) + b1f) * mask4)  -> split bf16
// MODE 3: out = z + (alpha*rp + 1) * (((hid @ w2) + b2f) * mask)
#define PITCH 40
template<int MODE>
__global__ __launch_bounds__(256)
void tgemm_kernel(const float* __restrict__ bias,
                  const float* __restrict__ xin,
                  const float* __restrict__ alpha,
                  float* __restrict__ dout) {
    constexpr int KT  = (MODE == 3) ? 2048 : 512;
    constexpr int NCH = KT / 32;
    const __nv_bfloat16* Ahg = (MODE==0)?g_h_h:(MODE==1)?g_o_h:(MODE==2)?g_hm_h:g_hid_h;
    const __nv_bfloat16* Alg = (MODE==0)?g_h_l:(MODE==1)?g_o_l:(MODE==2)?g_hm_l:g_hid_l;
    const __nv_bfloat16* Bhg = (MODE==0)?g_wqkvT_h:(MODE==1)?g_woT_h:(MODE==2)?g_w1T_h:g_w2T_h;
    const __nv_bfloat16* Blg = (MODE==0)?g_wqkvT_l:(MODE==1)?g_woT_l:(MODE==2)?g_w1T_l:g_w2T_l;
    extern __shared__ __nv_bfloat16 sm[];
    __nv_bfloat16* sAh = sm;                    // [128][PITCH]
    __nv_bfloat16* sAl = sm + 128*PITCH;
    __nv_bfloat16* sBh = sm + 2*128*PITCH;
    __nv_bfloat16* sBl = sm + 3*128*PITCH;
    int tid = threadIdx.x;          // 256
    int lane = tid & 31, w = tid >> 5;
    int wm = w & 1, wn = w >> 1;    // warp tile: rows wm*64..+64, cols wn*32..+32
    int m0 = blockIdx.y * 128;
    int n0 = blockIdx.x * 128;

    float acc[4][4][4] = {};

    // gmem load indices: 2 uint4 per tile per thread
    int lrow = tid >> 2, lq = tid & 3;           // +256: row+64
    const __nv_bfloat16* pAh = Ahg + (size_t)(m0 + lrow)*KT + lq*8;
    const __nv_bfloat16* pAl = Alg + (size_t)(m0 + lrow)*KT + lq*8;
    const __nv_bfloat16* pBh = Bhg + (size_t)(n0 + lrow)*KT + lq*8;
    const __nv_bfloat16* pBl = Blg + (size_t)(n0 + lrow)*KT + lq*8;
    uint32_t soff0 = lrow*PITCH + lq*8;
    uint32_t soff1 = (lrow + 64)*PITCH + lq*8;

    uint32_t sb = smem_u32(sm);
    // ldmatrix addresses
    uint32_t aoffH = sb + ((wm*64 + (lane & 15))*PITCH + (lane >> 4)*8)*2;
    uint32_t aoffL = aoffH + 128*PITCH*2;
    uint32_t boffH = sb + 2*128*PITCH*2 + ((wn*32 + (lane & 7))*PITCH + ((lane >> 3) & 1)*8)*2;
    uint32_t boffL = boffH + 128*PITCH*2;

    for (int c = 0; c < NCH; c++) {
        size_t go = (size_t)c * 32;
        *(uint4*)(sAh + soff0) = *(const uint4*)(pAh + go);
        *(uint4*)(sAh + soff1) = *(const uint4*)(pAh + go + (size_t)64*KT);
        *(uint4*)(sAl + soff0) = *(const uint4*)(pAl + go);
        *(uint4*)(sAl + soff1) = *(const uint4*)(pAl + go + (size_t)64*KT);
        *(uint4*)(sBh + soff0) = *(const uint4*)(pBh + go);
        *(uint4*)(sBh + soff1) = *(const uint4*)(pBh + go + (size_t)64*KT);
        *(uint4*)(sBl + soff0) = *(const uint4*)(pBl + go);
        *(uint4*)(sBl + soff1) = *(const uint4*)(pBl + go + (size_t)64*KT);
        __syncthreads();
        #pragma unroll
        for (int kk = 0; kk < 2; kk++) {
            uint32_t ah[4][4], al[4][4], bh[4][2], bl[4][2];
            #pragma unroll
            for (int mt = 0; mt < 4; mt++) {
                ldsm_x4(ah[mt], aoffH + (mt*16*PITCH + kk*16)*2);
                ldsm_x4(al[mt], aoffL + (mt*16*PITCH + kk*16)*2);
            }
            #pragma unroll
            for (int nt = 0; nt < 4; nt++) {
                ldsm_x2(bh[nt], boffH + (nt*8*PITCH + kk*16)*2);
                ldsm_x2(bl[nt], boffL + (nt*8*PITCH + kk*16)*2);
            }
            #pragma unroll
            for (int mt = 0; mt < 4; mt++)
                #pragma unroll
                for (int nt = 0; nt < 4; nt++) {
                    mma16816(acc[mt][nt], ah[mt], bh[nt]);
                    mma16816(acc[mt][nt], ah[mt], bl[nt]);
                    mma16816(acc[mt][nt], al[mt], bh[nt]);
                }
        }
        __syncthreads();
    }

    // ---------------- epilogue from c-fragments ----------------
    float a0 = (MODE == 3) ? alpha[0] : 0.f;
    #pragma unroll
    for (int mt = 0; mt < 4; mt++) {
        #pragma unroll
        for (int p = 0; p < 2; p++) {
            int row = m0 + wm*64 + mt*16 + (lane >> 2) + p*8;
            int dt = g_dtok[row];
            float gate = (MODE == 3) ? (a0 * g_rp[row] + 1.f) : 0.f;
            #pragma unroll
            for (int nt = 0; nt < 4; nt++) {
                #pragma unroll
                for (int e = 0; e < 2; e++) {
                    int c2 = n0 + wn*32 + nt*8 + (lane & 3)*2 + e;
                    float v = acc[mt][nt][p*2 + e];
                    if constexpr (MODE == 0) {
                        int cc = c2 & 511;
                        v = (cc < dt) ? v : 0.f;
                        int sel = c2 >> 9;
                        int hh = cc >> 6, dd = cc & 63;
                        int bidx = row >> 11, n = row & (NN-1);
                        float* dst = (sel == 0) ? g_q : (sel == 1) ? g_k : g_v;
                        dst[(((size_t)(bidx*HH + hh))*NN + n)*64 + dd] = v;
                    } else if constexpr (MODE == 1) {
                        v += bias[c2];
                        v = (c2 < dt) ? v : 0.f;
                        g_z[(size_t)row*DD + c2] = xin[(size_t)row*DD + c2] + v;
                    } else if constexpr (MODE == 2) {
                        v += bias[c2];
                        v = (c2 < 4*dt) ? v : 0.f;
                        float gv = gelu_f(v);
                        __nv_bfloat16 h, l; bf16_split(gv, h, l);
                        g_hid_h[(size_t)row*RD + c2] = h;
                        g_hid_l[(size_t)row*RD + c2] = l;
                    } else {
                        v += bias[c2];
                        v = (c2 < dt) ? v : 0.f;
                        dout[(size_t)row*DD + c2] = g_z[(size_t)row*DD + c2] + gate * v;
                    }
                }
            }
        }
    }
}

// ---------------- flash attention fp32: 128 q-rows per CTA, 64-key tiles ----------------
__global__ __launch_bounds__(256)
void attn_kernel() {
    extern __shared__ float smf[];
    float* Qs = smf;                     // [64][128] kk-major
    float* Ks = Qs + 64*128;             // [64][64]  kk-major
    float* Vs = Ks + 64*64;              // [64][68]
    float* Ps = Vs + 64*68;              // [128][68]
    int bh = blockIdx.y;
    int b = bh >> 3;
    int h = bh & 7;
    int m0 = blockIdx.x * 128;
    int tid = threadIdx.x;               // 256
    int tx = tid & 15, ty = tid >> 4;
    const float* qb = g_q + (size_t)bh * NN * 64;
    const float* kb = g_k + (size_t)bh * NN * 64;
    const float* vb = g_v + (size_t)bh * NN * 64;
    {
        int r = tid & 127;
        int kkbase = (tid >> 7) * 32;
        #pragma unroll
        for (int i = 0; i < 8; i++) {
            float4 qv = *(const float4*)&qb[(size_t)(m0+r)*64 + kkbase + i*4];
            Qs[(kkbase+i*4+0)*128 + r] = qv.x;
            Qs[(kkbase+i*4+1)*128 + r] = qv.y;
            Qs[(kkbase+i*4+2)*128 + r] = qv.z;
            Qs[(kkbase+i*4+3)*128 + r] = qv.w;
        }
    }
    float mold[8], lsum[8], O[8][4];
    #pragma unroll
    for (int i=0;i<8;i++){ mold[i] = -1e30f; lsum[i]=0.f;
        #pragma unroll
        for (int j=0;j<4;j++) O[i][j]=0.f; }
    __syncthreads();
    for (int n0 = 0; n0 < NN; n0 += 64) {
        {
            int c = tid & 63;
            int kk4 = (tid >> 6) * 16;
            #pragma unroll
            for (int i = 0; i < 4; i++) {
                float4 kv = *(const float4*)&kb[(size_t)(n0+c)*64 + kk4 + i*4];
                Ks[(kk4+i*4+0)*64 + c] = kv.x;
                Ks[(kk4+i*4+1)*64 + c] = kv.y;
                Ks[(kk4+i*4+2)*64 + c] = kv.z;
                Ks[(kk4+i*4+3)*64 + c] = kv.w;
                float4 vv = *(const float4*)&vb[(size_t)(n0+c)*64 + kk4 + i*4];
                *(float4*)&Vs[c*68 + kk4 + i*4] = vv;
            }
        }
        __syncthreads();
        float S[8][4] = {};
        #pragma unroll 8
        for (int kk = 0; kk < 64; kk++) {
            float4 a0 = *(float4*)&Qs[kk*128 + ty*4];
            float4 a1 = *(float4*)&Qs[kk*128 + 64 + ty*4];
            float4 bk = *(float4*)&Ks[kk*64 + tx*4];
            float ar[8] = {a0.x,a0.y,a0.z,a0.w,a1.x,a1.y,a1.z,a1.w};
            float br[4] = {bk.x,bk.y,bk.z,bk.w};
            #pragma unroll
            for (int i2=0;i2<8;i2++)
                #pragma unroll
                for (int j2=0;j2<4;j2++)
                    S[i2][j2] += ar[i2]*br[j2];
        }
        #pragma unroll
        for (int i = 0; i < 8; i++) {
            #pragma unroll
            for (int j = 0; j < 4; j++) S[i][j] *= 0.125f;  // 1/sqrt(64)
            float mx = fmaxf(fmaxf(S[i][0],S[i][1]), fmaxf(S[i][2],S[i][3]));
            for (int o = 8; o; o >>= 1) mx = fmaxf(mx, __shfl_xor_sync(0xffffffffu, mx, o));
            float mn = fmaxf(mold[i], mx);
            float corr = __expf(mold[i] - mn);
            float rs = 0.f;
            #pragma unroll
            for (int j = 0; j < 4; j++) { float p = __expf(S[i][j]-mn); S[i][j]=p; rs += p; }
            for (int o = 8; o; o >>= 1) rs += __shfl_xor_sync(0xffffffffu, rs, o);
            lsum[i] = lsum[i]*corr + rs;
            #pragma unroll
            for (int j = 0; j < 4; j++) O[i][j] *= corr;
            mold[i] = mn;
        }
        #pragma unroll
        for (int i=0;i<8;i++) {
            int ri = ty*4 + (i & 3) + (i >> 2) * 64;
            #pragma unroll
            for (int j=0;j<4;j++)
                Ps[ri*68 + tx*4+j] = S[i][j];
        }
        __syncthreads();
        #pragma unroll 8
        for (int c = 0; c < 64; c++) {
            float4 vv = *(float4*)&Vs[c*68 + tx*4];
            float pr[8];
            #pragma unroll
            for (int i=0;i<8;i++) {
                int ri = ty*4 + (i & 3) + (i >> 2) * 64;
                pr[i] = Ps[ri*68 + c];
            }
            float vr[4] = {vv.x,vv.y,vv.z,vv.w};
            #pragma unroll
            for (int i2=0;i2<8;i2++)
                #pragma unroll
                for (int j2=0;j2<4;j2++)
                    O[i2][j2] += pr[i2]*vr[j2];
        }
        __syncthreads();
    }
    #pragma unroll
    for (int i = 0; i < 8; i++) {
        int ri = ty*4 + (i & 3) + (i >> 2) * 64;
        int n = m0 + ri;
        int row = b*NN + n;
        int dt = g_dtok[row];
        float inv = 1.f / lsum[i];
        #pragma unroll
        for (int j = 0; j < 4; j++) {
            int feat = h*64 + tx*4 + j;
            float vv = (feat < dt) ? O[i][j]*inv : 0.f;
            __nv_bfloat16 hh, ll; bf16_split(vv, hh, ll);
            g_o_h[(size_t)row*DD + feat] = hh;
            g_o_l[(size_t)row*DD + feat] = ll;
        }
    }
}

// extra outputs (assigned, rp) — reference returns the full tuple
__global__ void extras_kernel(float* dout, int out_size) {
    int i = blockIdx.x * blockDim.x + threadIdx.x;
    if (i >= MROWS) return;
    const int base = MROWS*DD;
    if (out_size >= base + MROWS)   dout[base + i] = (float)g_assigned[i];
    if (out_size >= base + 2*MROWS) dout[base + MROWS + i] = g_rp[i];
}

extern "C" void kernel_launch(void* const* d_in, const int* in_sizes, int n_in,
                              void* d_out, int out_size) {
    const float* x    = (const float*)d_in[0];
    const float* r_w  = (const float*)d_in[1];
    const float* r_b  = (const float*)d_in[2];
    const float* g1   = (const float*)d_in[3];
    const float* b1   = (const float*)d_in[4];
    const float* g2   = (const float*)d_in[5];
    const float* b2   = (const float*)d_in[6];
    const float* wqkv = (const float*)d_in[7];
    const float* wo   = (const float*)d_in[8];
    const float* bo   = (const float*)d_in[9];
    const float* w1   = (const float*)d_in[10];
    const float* b1f  = (const float*)d_in[11];
    const float* w2   = (const float*)d_in[12];
    const float* b2f  = (const float*)d_in[13];
    const float* alpha= (const float*)d_in[14];
    float* out = (float*)d_out;

    constexpr int TG_SMEM = 4 * 128 * PITCH * 2;  // 40960 B
    constexpr int attn_smem = (64*128 + 64*64 + 64*68 + 128*68) * 4;  // 101376 B
    cudaFuncSetAttribute(attn_kernel, cudaFuncAttributeMaxDynamicSharedMemorySize, attn_smem);

    router_kernel<<<MROWS/4, 128>>>(x, r_w, r_b);
    assign_kernel<<<BB, 1024>>>();
    wconv_kernel<0><<<dim3(1536/32, 512/32),  dim3(32,8)>>>(wqkv);
    wconv_kernel<1><<<dim3(512/32,  512/32),  dim3(32,8)>>>(wo);
    wconv_kernel<2><<<dim3(2048/32, 512/32),  dim3(32,8)>>>(w1);
    wconv_kernel<3><<<dim3(512/32,  2048/32), dim3(32,8)>>>(w2);
    ln_mask_kernel<0><<<MROWS, 128>>>(x, g1, b1);
    tgemm_kernel<0><<<dim3(1536/128, MROWS/128), 256, TG_SMEM>>>(nullptr, nullptr, nullptr, nullptr);
    attn_kernel<<<dim3(NN/128, BB*HH), 256, attn_smem>>>();
    tgemm_kernel<1><<<dim3(512/128, MROWS/128), 256, TG_SMEM>>>(bo, x, nullptr, nullptr);
    ln_mask_kernel<1><<<MROWS, 128>>>(nullptr, g2, b2);
    tgemm_kernel<2><<<dim3(2048/128, MROWS/128), 256, TG_SMEM>>>(b1f, nullptr, nullptr, nullptr);
    tgemm_kernel<3><<<dim3(512/128, MROWS/128), 256, TG_SMEM>>>(b2f, nullptr, alpha, out);
    if (out_size > MROWS*DD)
        extras_kernel<<<(MROWS+255)/256, 256>>>(out, out_size);
}

// round 8
// speedup vs baseline: 1.9635x; 1.2607x over previous
#include <cuda_runtime.h>
#include <cuda_bf16.h>
#include <math.h>
#include <stdint.h>

#define BB 4
#define NN 2048
#define DD 512
#define HH 8
#define EE 4
#define RD 2048
#define MROWS (BB*NN)

// ---------------- scratch (device globals: no runtime allocation) ----------------
__device__ float g_probs[MROWS*EE];
__device__ int   g_assigned[MROWS];
__device__ float g_rp[MROWS];
__device__ int   g_dtok[MROWS];
__device__ float g_z[MROWS*DD];
// packed split-bf16 q/k/v: word = bits(hi) | bits(lo)<<16, layout [bh][n][64]
__device__ uint32_t g_q_p[MROWS*DD];
__device__ uint32_t g_k_p[MROWS*DD];
__device__ uint32_t g_v_p[MROWS*DD];
// split-bf16 activations (hi/lo)
__device__ __nv_bfloat16 g_h_h[MROWS*DD],  g_h_l[MROWS*DD];
__device__ __nv_bfloat16 g_o_h[MROWS*DD],  g_o_l[MROWS*DD];
__device__ __nv_bfloat16 g_hm_h[MROWS*DD], g_hm_l[MROWS*DD];
__device__ __nv_bfloat16 g_hid_h[(size_t)MROWS*RD], g_hid_l[(size_t)MROWS*RD];
// transposed split-bf16 weights  Wt[n][k]
__device__ __nv_bfloat16 g_wqkvT_h[1536*512], g_wqkvT_l[1536*512];
__device__ __nv_bfloat16 g_woT_h[512*512],    g_woT_l[512*512];
__device__ __nv_bfloat16 g_w1T_h[2048*512],   g_w1T_l[2048*512];
__device__ __nv_bfloat16 g_w2T_h[512*2048],   g_w2T_l[512*2048];

// ---------------- PTX helpers (baseline ISA only: ldmatrix + mma.sync) ----------------
__device__ __forceinline__ uint32_t smem_u32(const void* p) {
    uint32_t a;
    asm("{ .reg .u64 t; cvta.to.shared.u64 t, %1; cvt.u32.u64 %0, t; }" : "=r"(a) : "l"(p));
    return a;
}
__device__ __forceinline__ void ldsm_x4(uint32_t* r, uint32_t addr) {
    asm volatile("ldmatrix.sync.aligned.m8n8.x4.shared.b16 {%0,%1,%2,%3}, [%4];"
                 : "=r"(r[0]), "=r"(r[1]), "=r"(r[2]), "=r"(r[3]) : "r"(addr));
}
__device__ __forceinline__ void ldsm_x2(uint32_t* r, uint32_t addr) {
    asm volatile("ldmatrix.sync.aligned.m8n8.x2.shared.b16 {%0,%1}, [%2];"
                 : "=r"(r[0]), "=r"(r[1]) : "r"(addr));
}
__device__ __forceinline__ void mma16816(float* c, const uint32_t* a, const uint32_t* b) {
    asm volatile(
        "mma.sync.aligned.m16n8k16.row.col.f32.bf16.bf16.f32 "
        "{%0,%1,%2,%3}, {%4,%5,%6,%7}, {%8,%9}, {%0,%1,%2,%3};"
        : "+f"(c[0]), "+f"(c[1]), "+f"(c[2]), "+f"(c[3])
        : "r"(a[0]), "r"(a[1]), "r"(a[2]), "r"(a[3]), "r"(b[0]), "r"(b[1]));
}
__device__ __forceinline__ void bf16_split(float v, __nv_bfloat16& h, __nv_bfloat16& l) {
    h = __float2bfloat16(v);
    l = __float2bfloat16(v - __bfloat162float(h));
}
__device__ __forceinline__ uint32_t pack_split(float v) {
    __nv_bfloat16 h, l; bf16_split(v, h, l);
    return (uint32_t)__bfloat16_as_ushort(h) | ((uint32_t)__bfloat16_as_ushort(l) << 16);
}
// fast exp on fma pipe (no MUFU): 2^f Taylor deg-6, exponent-bit scaling
__device__ __forceinline__ float fast_exp(float x) {
    x = fmaxf(x, -87.0f);
    float t = x * 1.4426950408889634f;
    float r = rintf(t);
    float f = t - r;
    float p = 1.5403530393381609e-4f;
    p = fmaf(p, f, 1.3333558146428443e-3f);
    p = fmaf(p, f, 9.6181291076284772e-3f);
    p = fmaf(p, f, 5.5504108664821580e-2f);
    p = fmaf(p, f, 2.4022650695910071e-1f);
    p = fmaf(p, f, 6.9314718055994531e-1f);
    p = fmaf(p, f, 1.0f);
    int i = (int)r;
    return p * __int_as_float((i + 127) << 23);
}

// ---------------- router: logits + softmax ----------------
__global__ void router_kernel(const float* __restrict__ x,
                              const float* __restrict__ rw,
                              const float* __restrict__ rb) {
    int gw = (blockIdx.x * blockDim.x + threadIdx.x) >> 5;
    int lane = threadIdx.x & 31;
    if (gw >= MROWS) return;
    const float* xr = x + (size_t)gw * DD;
    float a0=0.f,a1=0.f,a2=0.f,a3=0.f;
    for (int k = lane; k < DD; k += 32) {
        float xv = xr[k];
        const float* w = rw + (size_t)k*EE;
        a0 += xv*w[0]; a1 += xv*w[1]; a2 += xv*w[2]; a3 += xv*w[3];
    }
    for (int o = 16; o; o >>= 1) {
        a0 += __shfl_xor_sync(0xffffffffu, a0, o);
        a1 += __shfl_xor_sync(0xffffffffu, a1, o);
        a2 += __shfl_xor_sync(0xffffffffu, a2, o);
        a3 += __shfl_xor_sync(0xffffffffu, a3, o);
    }
    if (lane == 0) {
        float l0=a0+rb[0], l1=a1+rb[1], l2=a2+rb[2], l3=a3+rb[3];
        float mx = fmaxf(fmaxf(l0,l1), fmaxf(l2,l3));
        float e0=expf(l0-mx), e1=expf(l1-mx), e2=expf(l2-mx), e3=expf(l3-mx);
        float inv = 1.f/(e0+e1+e2+e3);
        float* p = g_probs + (size_t)gw*EE;
        p[0]=e0*inv; p[1]=e1*inv; p[2]=e2*inv; p[3]=e3*inv;
    }
}

// ---------------- expert-preferred greedy assignment (bitonic top-k) ----------------
__global__ void assign_kernel() {
    __shared__ unsigned long long keys[NN];
    __shared__ int asg[NN];
    int b = blockIdx.x;
    int t = threadIdx.x;
    for (int i = t; i < NN; i += 1024) asg[i] = -1;
    const int caps[EE] = {1024, 512, 256, 256};
    for (int e = EE-1; e >= 1; e--) {
        __syncthreads();
        for (int i = t; i < NN; i += 1024) {
            unsigned pb = __float_as_uint(g_probs[((size_t)b*NN+i)*EE + e]);
            unsigned long long key =
                ((unsigned long long)(asg[i] < 0 ? 1u : 0u) << 63) |
                ((unsigned long long)pb << 16) |
                (unsigned long long)(NN-1-i);
            keys[i] = key;
        }
        __syncthreads();
        for (int k = 2; k <= NN; k <<= 1) {
            for (int j = k >> 1; j > 0; j >>= 1) {
                for (int ii = t; ii < NN; ii += 1024) {
                    int l = ii ^ j;
                    if (l > ii) {
                        unsigned long long va = keys[ii], vb = keys[l];
                        bool desc = ((ii & k) == 0);
                        if (desc ? (va < vb) : (va > vb)) { keys[ii]=vb; keys[l]=va; }
                    }
                }
                __syncthreads();
            }
        }
        int cap = caps[e];
        for (int i = t; i < cap; i += 1024) {
            int idx = NN-1 - (int)(keys[i] & 0xffffu);
            asg[idx] = e;
        }
    }
    __syncthreads();
    for (int i = t; i < NN; i += 1024) {
        int a = asg[i]; if (a < 0) a = 0;
        g_assigned[b*NN+i] = a;
        g_rp[b*NN+i] = g_probs[((size_t)b*NN+i)*EE + a];
        g_dtok[b*NN+i] = 64 << a;
    }
}

// ---------------- weight transpose + split-bf16 convert: Wt[n][k] = W[k][n] ----------------
template<int MODE>
__global__ void wconv_kernel(const float* __restrict__ W) {
    constexpr int K = (MODE==3)?2048:512;
    constexpr int N = (MODE==0)?1536:(MODE==2)?2048:512;
    __nv_bfloat16* oh = (MODE==0)?g_wqkvT_h:(MODE==1)?g_woT_h:(MODE==2)?g_w1T_h:g_w2T_h;
    __nv_bfloat16* ol = (MODE==0)?g_wqkvT_l:(MODE==1)?g_woT_l:(MODE==2)?g_w1T_l:g_w2T_l;
    __shared__ float tbuf[32][33];
    int n0 = blockIdx.x*32, k0 = blockIdx.y*32;
    int tx = threadIdx.x, ty = threadIdx.y;
    #pragma unroll
    for (int i = 0; i < 4; i++)
        tbuf[ty+i*8][tx] = W[(size_t)(k0+ty+i*8)*N + n0+tx];
    __syncthreads();
    #pragma unroll
    for (int i = 0; i < 4; i++) {
        int n = n0 + ty + i*8, k = k0 + tx;
        float v = tbuf[tx][ty+i*8];
        __nv_bfloat16 h, l; bf16_split(v, h, l);
        oh[(size_t)n*K + k] = h;
        ol[(size_t)n*K + k] = l;
    }
}

// ---------------- layernorm + feature mask -> split bf16 ----------------
template<int LM>
__global__ void ln_mask_kernel(const float* __restrict__ xin,
                               const float* __restrict__ g,
                               const float* __restrict__ be) {
    int tok = blockIdx.x;
    int t = threadIdx.x;  // 128
    const float* in = (LM == 0) ? xin : g_z;
    __nv_bfloat16* oh = (LM == 0) ? g_h_h : g_hm_h;
    __nv_bfloat16* ol = (LM == 0) ? g_h_l : g_hm_l;
    const float* xr = in + (size_t)tok * DD;
    float v[4]; float s = 0.f;
    #pragma unroll
    for (int i = 0; i < 4; i++) { v[i] = xr[t + 128*i]; s += v[i]; }
    __shared__ float red[4];
    for (int o = 16; o; o >>= 1) s += __shfl_xor_sync(0xffffffffu, s, o);
    if ((t & 31) == 0) red[t >> 5] = s;
    __syncthreads();
    float mu = (red[0]+red[1]+red[2]+red[3]) * (1.f/DD);
    float s2 = 0.f;
    #pragma unroll
    for (int i = 0; i < 4; i++) { float d = v[i]-mu; s2 += d*d; }
    __syncthreads();
    for (int o = 16; o; o >>= 1) s2 += __shfl_xor_sync(0xffffffffu, s2, o);
    if ((t & 31) == 0) red[t >> 5] = s2;
    __syncthreads();
    float var = (red[0]+red[1]+red[2]+red[3]) * (1.f/DD);
    float rs = rsqrtf(var + 1e-5f);
    int dt = g_dtok[tok];
    #pragma unroll
    for (int i = 0; i < 4; i++) {
        int c = t + 128*i;
        float val = (c < dt) ? ((v[i]-mu)*rs*g[c] + be[c]) : 0.f;
        __nv_bfloat16 h, l; bf16_split(val, h, l);
        oh[(size_t)tok*DD + c] = h;
        ol[(size_t)tok*DD + c] = l;
    }
}

__device__ __forceinline__ float gelu_f(float x) {
    float x3 = x*x*x;
    return 0.5f * x * (1.f + tanhf(0.7978845608028654f * (x + 0.044715f * x3)));
}

// ---------------- HMMA split-bf16 GEMM: 128x128 CTA tile, 8 warps x (64x32) ----------------
#define PITCH 40
template<int MODE>
__global__ __launch_bounds__(256)
void tgemm_kernel(const float* __restrict__ bias,
                  const float* __restrict__ xin,
                  const float* __restrict__ alpha,
                  float* __restrict__ dout) {
    constexpr int KT  = (MODE == 3) ? 2048 : 512;
    constexpr int NCH = KT / 32;
    const __nv_bfloat16* Ahg = (MODE==0)?g_h_h:(MODE==1)?g_o_h:(MODE==2)?g_hm_h:g_hid_h;
    const __nv_bfloat16* Alg = (MODE==0)?g_h_l:(MODE==1)?g_o_l:(MODE==2)?g_hm_l:g_hid_l;
    const __nv_bfloat16* Bhg = (MODE==0)?g_wqkvT_h:(MODE==1)?g_woT_h:(MODE==2)?g_w1T_h:g_w2T_h;
    const __nv_bfloat16* Blg = (MODE==0)?g_wqkvT_l:(MODE==1)?g_woT_l:(MODE==2)?g_w1T_l:g_w2T_l;
    extern __shared__ __nv_bfloat16 sm[];
    __nv_bfloat16* sAh = sm;                    // [128][PITCH]
    __nv_bfloat16* sAl = sm + 128*PITCH;
    __nv_bfloat16* sBh = sm + 2*128*PITCH;
    __nv_bfloat16* sBl = sm + 3*128*PITCH;
    int tid = threadIdx.x;          // 256
    int lane = tid & 31, w = tid >> 5;
    int wm = w & 1, wn = w >> 1;
    int m0 = blockIdx.y * 128;
    int n0 = blockIdx.x * 128;

    float acc[4][4][4] = {};

    int lrow = tid >> 2, lq = tid & 3;
    const __nv_bfloat16* pAh = Ahg + (size_t)(m0 + lrow)*KT + lq*8;
    const __nv_bfloat16* pAl = Alg + (size_t)(m0 + lrow)*KT + lq*8;
    const __nv_bfloat16* pBh = Bhg + (size_t)(n0 + lrow)*KT + lq*8;
    const __nv_bfloat16* pBl = Blg + (size_t)(n0 + lrow)*KT + lq*8;
    uint32_t soff0 = lrow*PITCH + lq*8;
    uint32_t soff1 = (lrow + 64)*PITCH + lq*8;

    uint32_t sb = smem_u32(sm);
    uint32_t aoffH = sb + ((wm*64 + (lane & 15))*PITCH + (lane >> 4)*8)*2;
    uint32_t aoffL = aoffH + 128*PITCH*2;
    uint32_t boffH = sb + 2*128*PITCH*2 + ((wn*32 + (lane & 7))*PITCH + ((lane >> 3) & 1)*8)*2;
    uint32_t boffL = boffH + 128*PITCH*2;

    for (int c = 0; c < NCH; c++) {
        size_t go = (size_t)c * 32;
        *(uint4*)(sAh + soff0) = *(const uint4*)(pAh + go);
        *(uint4*)(sAh + soff1) = *(const uint4*)(pAh + go + (size_t)64*KT);
        *(uint4*)(sAl + soff0) = *(const uint4*)(pAl + go);
        *(uint4*)(sAl + soff1) = *(const uint4*)(pAl + go + (size_t)64*KT);
        *(uint4*)(sBh + soff0) = *(const uint4*)(pBh + go);
        *(uint4*)(sBh + soff1) = *(const uint4*)(pBh + go + (size_t)64*KT);
        *(uint4*)(sBl + soff0) = *(const uint4*)(pBl + go);
        *(uint4*)(sBl + soff1) = *(const uint4*)(pBl + go + (size_t)64*KT);
        __syncthreads();
        #pragma unroll
        for (int kk = 0; kk < 2; kk++) {
            uint32_t ah[4][4], al[4][4], bh[4][2], bl[4][2];
            #pragma unroll
            for (int mt = 0; mt < 4; mt++) {
                ldsm_x4(ah[mt], aoffH + (mt*16*PITCH + kk*16)*2);
                ldsm_x4(al[mt], aoffL + (mt*16*PITCH + kk*16)*2);
            }
            #pragma unroll
            for (int nt = 0; nt < 4; nt++) {
                ldsm_x2(bh[nt], boffH + (nt*8*PITCH + kk*16)*2);
                ldsm_x2(bl[nt], boffL + (nt*8*PITCH + kk*16)*2);
            }
            #pragma unroll
            for (int mt = 0; mt < 4; mt++)
                #pragma unroll
                for (int nt = 0; nt < 4; nt++) {
                    mma16816(acc[mt][nt], ah[mt], bh[nt]);
                    mma16816(acc[mt][nt], ah[mt], bl[nt]);
                    mma16816(acc[mt][nt], al[mt], bh[nt]);
                }
        }
        __syncthreads();
    }

    float a0 = (MODE == 3) ? alpha[0] : 0.f;
    #pragma unroll
    for (int mt = 0; mt < 4; mt++) {
        #pragma unroll
        for (int p = 0; p < 2; p++) {
            int row = m0 + wm*64 + mt*16 + (lane >> 2) + p*8;
            int dt = g_dtok[row];
            float gate = (MODE == 3) ? (a0 * g_rp[row] + 1.f) : 0.f;
            #pragma unroll
            for (int nt = 0; nt < 4; nt++) {
                #pragma unroll
                for (int e = 0; e < 2; e++) {
                    int c2 = n0 + wn*32 + nt*8 + (lane & 3)*2 + e;
                    float v = acc[mt][nt][p*2 + e];
                    if constexpr (MODE == 0) {
                        int cc = c2 & 511;
                        v = (cc < dt) ? v : 0.f;
                        int sel = c2 >> 9;
                        int hh = cc >> 6, dd = cc & 63;
                        int bidx = row >> 11, n = row & (NN-1);
                        uint32_t* dst = (sel == 0) ? g_q_p : (sel == 1) ? g_k_p : g_v_p;
                        dst[(((size_t)(bidx*HH + hh))*NN + n)*64 + dd] = pack_split(v);
                    } else if constexpr (MODE == 1) {
                        v += bias[c2];
                        v = (c2 < dt) ? v : 0.f;
                        g_z[(size_t)row*DD + c2] = xin[(size_t)row*DD + c2] + v;
                    } else if constexpr (MODE == 2) {
                        v += bias[c2];
                        v = (c2 < 4*dt) ? v : 0.f;
                        float gv = gelu_f(v);
                        __nv_bfloat16 h, l; bf16_split(gv, h, l);
                        g_hid_h[(size_t)row*RD + c2] = h;
                        g_hid_l[(size_t)row*RD + c2] = l;
                    } else {
                        v += bias[c2];
                        v = (c2 < dt) ? v : 0.f;
                        dout[(size_t)row*DD + c2] = g_z[(size_t)row*DD + c2] + gate * v;
                    }
                }
            }
        }
    }
}

// ---------------- HMMA flash attention: 128 q-rows/CTA, 64-key tiles, split-bf16 ----------------
#define APITCH 72
__global__ __launch_bounds__(256)
void attn_kernel() {
    // smH: Qh[128][72] then {Kh[64][72], Vh[64][72]};  smL: same for lo plane
    __shared__ uint16_t smH[128*APITCH];
    __shared__ uint16_t smL[128*APITCH];
    int bh = blockIdx.y;
    int b = bh >> 3;
    int h = bh & 7;
    int m0 = blockIdx.x * 128;
    int tid = threadIdx.x;           // 256
    int lane = tid & 31, w = tid >> 5;
    const uint32_t* qp = g_q_p + (size_t)bh * NN * 64;
    const uint32_t* kp = g_k_p + (size_t)bh * NN * 64;
    const uint32_t* vp = g_v_p + (size_t)bh * NN * 64;

    // ---- fill Q tile (rows m0..m0+127), unpack hi/lo ----
    {
        int row = tid >> 1, hb = (tid & 1) * 32;
        const uint4* src = (const uint4*)(qp + (size_t)(m0 + row)*64 + hb);
        #pragma unroll
        for (int j = 0; j < 8; j++) {
            uint4 u = src[j];
            uint32_t ws[4] = {u.x, u.y, u.z, u.w};
            #pragma unroll
            for (int q = 0; q < 4; q++) {
                int d = hb + j*4 + q;
                smH[row*APITCH + d] = (uint16_t)(ws[q] & 0xFFFFu);
                smL[row*APITCH + d] = (uint16_t)(ws[q] >> 16);
            }
        }
    }
    __syncthreads();
    // ---- extract Q a-fragments (cached whole kernel) ----
    uint32_t qa_h[4][4], qa_l[4][4];
    {
        uint32_t qoffH = smem_u32(smH) + ((w*16 + (lane & 15))*APITCH + (lane >> 4)*8)*2;
        uint32_t qoffL = smem_u32(smL) + ((w*16 + (lane & 15))*APITCH + (lane >> 4)*8)*2;
        #pragma unroll
        for (int kc = 0; kc < 4; kc++) {
            ldsm_x4(qa_h[kc], qoffH + kc*16*2);
            ldsm_x4(qa_l[kc], qoffL + kc*16*2);
        }
    }
    __syncthreads();  // Q smem now reusable for K/V

    uint32_t kbH = smem_u32(smH) + ((lane & 7)*APITCH + ((lane >> 3) & 1)*8)*2;
    uint32_t kbL = smem_u32(smL) + ((lane & 7)*APITCH + ((lane >> 3) & 1)*8)*2;
    uint32_t vbH = smem_u32(smH) + ((64 + (lane & 7))*APITCH + ((lane >> 3) & 1)*8)*2;
    uint32_t vbL = smem_u32(smL) + ((64 + (lane & 7))*APITCH + ((lane >> 3) & 1)*8)*2;

    float O[8][4] = {};
    float mold0 = -1e30f, mold1 = -1e30f, lsum0 = 0.f, lsum1 = 0.f;

    for (int n0 = 0; n0 < NN; n0 += 64) {
        // ---- fill K tile [key][d] (rows 0..63) ----
        {
            int key = tid >> 2, part = (tid & 3)*16;
            const uint4* src = (const uint4*)(kp + (size_t)(n0 + key)*64 + part);
            #pragma unroll
            for (int j = 0; j < 4; j++) {
                uint4 u = src[j];
                uint32_t ws[4] = {u.x, u.y, u.z, u.w};
                #pragma unroll
                for (int q = 0; q < 4; q++) {
                    int d = part + j*4 + q;
                    smH[key*APITCH + d] = (uint16_t)(ws[q] & 0xFFFFu);
                    smL[key*APITCH + d] = (uint16_t)(ws[q] >> 16);
                }
            }
        }
        // ---- fill V tile transposed [d][key] at row offset 64 ----
        {
            int key = tid & 63, dbase = (tid >> 6)*16;
            const uint4* src = (const uint4*)(vp + (size_t)(n0 + key)*64 + dbase);
            #pragma unroll
            for (int j = 0; j < 4; j++) {
                uint4 u = src[j];
                uint32_t ws[4] = {u.x, u.y, u.z, u.w};
                #pragma unroll
                for (int q = 0; q < 4; q++) {
                    int d = dbase + j*4 + q;
                    smH[(64 + d)*APITCH + key] = (uint16_t)(ws[q] & 0xFFFFu);
                    smL[(64 + d)*APITCH + key] = (uint16_t)(ws[q] >> 16);
                }
            }
        }
        __syncthreads();

        // ---- S = Q K^T (split 3-term) ----
        float S[8][4] = {};
        #pragma unroll
        for (int kc = 0; kc < 4; kc++) {
            #pragma unroll
            for (int nt = 0; nt < 8; nt++) {
                uint32_t kb2[2], kl2[2];
                ldsm_x2(kb2, kbH + (nt*8*APITCH + kc*16)*2);
                ldsm_x2(kl2, kbL + (nt*8*APITCH + kc*16)*2);
                mma16816(S[nt], qa_h[kc], kb2);
                mma16816(S[nt], qa_h[kc], kl2);
                mma16816(S[nt], qa_l[kc], kb2);
            }
        }
        // ---- online softmax on fragments (fast_exp on fma pipe) ----
        float mx0 = -1e30f, mx1 = -1e30f;
        #pragma unroll
        for (int nt = 0; nt < 8; nt++) {
            S[nt][0] *= 0.125f; S[nt][1] *= 0.125f; S[nt][2] *= 0.125f; S[nt][3] *= 0.125f;
            mx0 = fmaxf(mx0, fmaxf(S[nt][0], S[nt][1]));
            mx1 = fmaxf(mx1, fmaxf(S[nt][2], S[nt][3]));
        }
        mx0 = fmaxf(mx0, __shfl_xor_sync(0xffffffffu, mx0, 1));
        mx0 = fmaxf(mx0, __shfl_xor_sync(0xffffffffu, mx0, 2));
        mx1 = fmaxf(mx1, __shfl_xor_sync(0xffffffffu, mx1, 1));
        mx1 = fmaxf(mx1, __shfl_xor_sync(0xffffffffu, mx1, 2));
        float mn0 = fmaxf(mold0, mx0), mn1 = fmaxf(mold1, mx1);
        float corr0 = fast_exp(mold0 - mn0), corr1 = fast_exp(mold1 - mn1);
        float rs0 = 0.f, rs1 = 0.f;
        #pragma unroll
        for (int nt = 0; nt < 8; nt++) {
            S[nt][0] = fast_exp(S[nt][0] - mn0); rs0 += S[nt][0];
            S[nt][1] = fast_exp(S[nt][1] - mn0); rs0 += S[nt][1];
            S[nt][2] = fast_exp(S[nt][2] - mn1); rs1 += S[nt][2];
            S[nt][3] = fast_exp(S[nt][3] - mn1); rs1 += S[nt][3];
        }
        rs0 += __shfl_xor_sync(0xffffffffu, rs0, 1);
        rs0 += __shfl_xor_sync(0xffffffffu, rs0, 2);
        rs1 += __shfl_xor_sync(0xffffffffu, rs1, 1);
        rs1 += __shfl_xor_sync(0xffffffffu, rs1, 2);
        lsum0 = lsum0*corr0 + rs0;
        lsum1 = lsum1*corr1 + rs1;
        #pragma unroll
        for (int nt = 0; nt < 8; nt++) {
            O[nt][0] *= corr0; O[nt][1] *= corr0; O[nt][2] *= corr1; O[nt][3] *= corr1;
        }
        mold0 = mn0; mold1 = mn1;

        // ---- O += P V (P from S fragments, split 3-term) ----
        #pragma unroll
        for (int kc = 0; kc < 4; kc++) {
            uint32_t pah[4], pal[4];
            #pragma unroll
            for (int half = 0; half < 2; half++) {
                int nt = 2*kc + half;
                __nv_bfloat16 h0,l0,h1,l1,h2,l2,h3,l3;
                bf16_split(S[nt][0], h0, l0);
                bf16_split(S[nt][1], h1, l1);
                bf16_split(S[nt][2], h2, l2);
                bf16_split(S[nt][3], h3, l3);
                pah[half*2+0] = (uint32_t)__bfloat16_as_ushort(h0) | ((uint32_t)__bfloat16_as_ushort(h1) << 16);
                pah[half*2+1] = (uint32_t)__bfloat16_as_ushort(h2) | ((uint32_t)__bfloat16_as_ushort(h3) << 16);
                pal[half*2+0] = (uint32_t)__bfloat16_as_ushort(l0) | ((uint32_t)__bfloat16_as_ushort(l1) << 16);
                pal[half*2+1] = (uint32_t)__bfloat16_as_ushort(l2) | ((uint32_t)__bfloat16_as_ushort(l3) << 16);
            }
            #pragma unroll
            for (int nt = 0; nt < 8; nt++) {
                uint32_t vh2[2], vl2[2];
                ldsm_x2(vh2, vbH + (nt*8*APITCH + kc*16)*2);
                ldsm_x2(vl2, vbL + (nt*8*APITCH + kc*16)*2);
                mma16816(O[nt], pah, vh2);
                mma16816(O[nt], pah, vl2);
                mma16816(O[nt], pal, vh2);
            }
        }
        __syncthreads();
    }

    // ---- normalize, mask, write split-bf16 o ----
    float inv0 = 1.f / lsum0, inv1 = 1.f / lsum1;
    int r0 = m0 + w*16 + (lane >> 2);
    int row0 = b*NN + r0, row1 = row0 + 8;
    int dt0 = g_dtok[row0], dt1 = g_dtok[row1];
    #pragma unroll
    for (int nt = 0; nt < 8; nt++) {
        #pragma unroll
        for (int e = 0; e < 2; e++) {
            int feat = h*64 + nt*8 + (lane & 3)*2 + e;
            float v0 = (feat < dt0) ? O[nt][e]*inv0 : 0.f;
            float v1 = (feat < dt1) ? O[nt][2+e]*inv1 : 0.f;
            __nv_bfloat16 hh, ll;
            bf16_split(v0, hh, ll);
            g_o_h[(size_t)row0*DD + feat] = hh;
            g_o_l[(size_t)row0*DD + feat] = ll;
            bf16_split(v1, hh, ll);
            g_o_h[(size_t)row1*DD + feat] = hh;
            g_o_l[(size_t)row1*DD + feat] = ll;
        }
    }
}

// extra outputs (assigned, rp) — reference returns the full tuple
__global__ void extras_kernel(float* dout, int out_size) {
    int i = blockIdx.x * blockDim.x + threadIdx.x;
    if (i >= MROWS) return;
    const int base = MROWS*DD;
    if (out_size >= base + MROWS)   dout[base + i] = (float)g_assigned[i];
    if (out_size >= base + 2*MROWS) dout[base + MROWS + i] = g_rp[i];
}

extern "C" void kernel_launch(void* const* d_in, const int* in_sizes, int n_in,
                              void* d_out, int out_size) {
    const float* x    = (const float*)d_in[0];
    const float* r_w  = (const float*)d_in[1];
    const float* r_b  = (const float*)d_in[2];
    const float* g1   = (const float*)d_in[3];
    const float* b1   = (const float*)d_in[4];
    const float* g2   = (const float*)d_in[5];
    const float* b2   = (const float*)d_in[6];
    const float* wqkv = (const float*)d_in[7];
    const float* wo   = (const float*)d_in[8];
    const float* bo   = (const float*)d_in[9];
    const float* w1   = (const float*)d_in[10];
    const float* b1f  = (const float*)d_in[11];
    const float* w2   = (const float*)d_in[12];
    const float* b2f  = (const float*)d_in[13];
    const float* alpha= (const float*)d_in[14];
    float* out = (float*)d_out;

    constexpr int TG_SMEM = 4 * 128 * PITCH * 2;  // 40960 B

    router_kernel<<<MROWS/4, 128>>>(x, r_w, r_b);
    assign_kernel<<<BB, 1024>>>();
    wconv_kernel<0><<<dim3(1536/32, 512/32),  dim3(32,8)>>>(wqkv);
    wconv_kernel<1><<<dim3(512/32,  512/32),  dim3(32,8)>>>(wo);
    wconv_kernel<2><<<dim3(2048/32, 512/32),  dim3(32,8)>>>(w1);
    wconv_kernel<3><<<dim3(512/32,  2048/32), dim3(32,8)>>>(w2);
    ln_mask_kernel<0><<<MROWS, 128>>>(x, g1, b1);
    tgemm_kernel<0><<<dim3(1536/128, MROWS/128), 256, TG_SMEM>>>(nullptr, nullptr, nullptr, nullptr);
    attn_kernel<<<dim3(NN/128, BB*HH), 256>>>();
    tgemm_kernel<1><<<dim3(512/128, MROWS/128), 256, TG_SMEM>>>(bo, x, nullptr, nullptr);
    ln_mask_kernel<1><<<MROWS, 128>>>(nullptr, g2, b2);
    tgemm_kernel<2><<<dim3(2048/128, MROWS/128), 256, TG_SMEM>>>(b1f, nullptr, nullptr, nullptr);
    tgemm_kernel<3><<<dim3(512/128, MROWS/128), 256, TG_SMEM>>>(b2f, nullptr, alpha, out);
    if (out_size > MROWS*DD)
        extras_kernel<<<(MROWS+255)/256, 256>>>(out, out_size);
}

// round 14
// speedup vs baseline: 3.4996x; 1.7823x over previous
#include <cuda_runtime.h>
#include <cuda_bf16.h>
#include <math.h>
#include <stdint.h>

#define BB 4
#define NN 2048
#define DD 512
#define HH 8
#define EE 4
#define RD 2048
#define MROWS (BB*NN)

// ---------------- scratch (device globals: no runtime allocation) ----------------
__device__ float g_probs[MROWS*EE];
__device__ int   g_assigned[MROWS];
__device__ float g_rp[MROWS];
__device__ int   g_perm[MROWS];      // rank -> global token index
__device__ float g_rp_p[MROWS];      // router prob at permuted rows
__device__ float g_z[MROWS*DD];      // permuted rows
// packed split-bf16 q/k/v: word = bits(hi) | bits(lo)<<16, layout [bh][rank][64]
__device__ uint32_t g_q_p[MROWS*DD];
__device__ uint32_t g_k_p[MROWS*DD];
__device__ uint32_t g_v_p[MROWS*DD];
// split-bf16 activations (hi/lo), permuted rows
__device__ __nv_bfloat16 g_h_h[MROWS*DD],  g_h_l[MROWS*DD];
__device__ __nv_bfloat16 g_o_h[MROWS*DD],  g_o_l[MROWS*DD];
__device__ __nv_bfloat16 g_hm_h[MROWS*DD], g_hm_l[MROWS*DD];
__device__ __nv_bfloat16 g_hid_h[(size_t)MROWS*RD], g_hid_l[(size_t)MROWS*RD];
// transposed split-bf16 weights  Wt[n][k]
__device__ __nv_bfloat16 g_wqkvT_h[1536*512], g_wqkvT_l[1536*512];
__device__ __nv_bfloat16 g_woT_h[512*512],    g_woT_l[512*512];
__device__ __nv_bfloat16 g_w1T_h[2048*512],   g_w1T_l[2048*512];
__device__ __nv_bfloat16 g_w2T_h[512*2048],   g_w2T_l[512*2048];

// segments per batch after sort: [0,256)->512, [256,512)->256, [512,1024)->128, [1024,2048)->64
__device__ __forceinline__ int dt_of_rank(int rr) {
    return (rr < 256) ? 512 : (rr < 512) ? 256 : (rr < 1024) ? 128 : 64;
}

// ---------------- PTX helpers (baseline ISA only: ldmatrix + mma.sync) ----------------
__device__ __forceinline__ uint32_t smem_u32(const void* p) {
    uint32_t a;
    asm("{ .reg .u64 t; cvta.to.shared.u64 t, %1; cvt.u32.u64 %0, t; }" : "=r"(a) : "l"(p));
    return a;
}
__device__ __forceinline__ void ldsm_x4(uint32_t* r, uint32_t addr) {
    asm volatile("ldmatrix.sync.aligned.m8n8.x4.shared.b16 {%0,%1,%2,%3}, [%4];"
                 : "=r"(r[0]), "=r"(r[1]), "=r"(r[2]), "=r"(r[3]) : "r"(addr));
}
__device__ __forceinline__ void ldsm_x2(uint32_t* r, uint32_t addr) {
    asm volatile("ldmatrix.sync.aligned.m8n8.x2.shared.b16 {%0,%1}, [%2];"
                 : "=r"(r[0]), "=r"(r[1]) : "r"(addr));
}
__device__ __forceinline__ void mma16816(float* c, const uint32_t* a, const uint32_t* b) {
    asm volatile(
        "mma.sync.aligned.m16n8k16.row.col.f32.bf16.bf16.f32 "
        "{%0,%1,%2,%3}, {%4,%5,%6,%7}, {%8,%9}, {%0,%1,%2,%3};"
        : "+f"(c[0]), "+f"(c[1]), "+f"(c[2]), "+f"(c[3])
        : "r"(a[0]), "r"(a[1]), "r"(a[2]), "r"(a[3]), "r"(b[0]), "r"(b[1]));
}
__device__ __forceinline__ void bf16_split(float v, __nv_bfloat16& h, __nv_bfloat16& l) {
    h = __float2bfloat16(v);
    l = __float2bfloat16(v - __bfloat162float(h));
}
__device__ __forceinline__ uint32_t pack_split(float v) {
    __nv_bfloat16 h, l; bf16_split(v, h, l);
    return (uint32_t)__bfloat16_as_ushort(h) | ((uint32_t)__bfloat16_as_ushort(l) << 16);
}
// fast exp on fma pipe (no MUFU)
__device__ __forceinline__ float fast_exp(float x) {
    x = fmaxf(x, -87.0f);
    float t = x * 1.4426950408889634f;
    float r = rintf(t);
    float f = t - r;
    float p = 1.5403530393381609e-4f;
    p = fmaf(p, f, 1.3333558146428443e-3f);
    p = fmaf(p, f, 9.6181291076284772e-3f);
    p = fmaf(p, f, 5.5504108664821580e-2f);
    p = fmaf(p, f, 2.4022650695910071e-1f);
    p = fmaf(p, f, 6.9314718055994531e-1f);
    p = fmaf(p, f, 1.0f);
    int i = (int)r;
    return p * __int_as_float((i + 127) << 23);
}

// ---------------- router: logits + softmax ----------------
__global__ void router_kernel(const float* __restrict__ x,
                              const float* __restrict__ rw,
                              const float* __restrict__ rb) {
    int gw = (blockIdx.x * blockDim.x + threadIdx.x) >> 5;
    int lane = threadIdx.x & 31;
    if (gw >= MROWS) return;
    const float* xr = x + (size_t)gw * DD;
    float a0=0.f,a1=0.f,a2=0.f,a3=0.f;
    for (int k = lane; k < DD; k += 32) {
        float xv = xr[k];
        const float* w = rw + (size_t)k*EE;
        a0 += xv*w[0]; a1 += xv*w[1]; a2 += xv*w[2]; a3 += xv*w[3];
    }
    for (int o = 16; o; o >>= 1) {
        a0 += __shfl_xor_sync(0xffffffffu, a0, o);
        a1 += __shfl_xor_sync(0xffffffffu, a1, o);
        a2 += __shfl_xor_sync(0xffffffffu, a2, o);
        a3 += __shfl_xor_sync(0xffffffffu, a3, o);
    }
    if (lane == 0) {
        float l0=a0+rb[0], l1=a1+rb[1], l2=a2+rb[2], l3=a3+rb[3];
        float mx = fmaxf(fmaxf(l0,l1), fmaxf(l2,l3));
        float e0=expf(l0-mx), e1=expf(l1-mx), e2=expf(l2-mx), e3=expf(l3-mx);
        float inv = 1.f/(e0+e1+e2+e3);
        float* p = g_probs + (size_t)gw*EE;
        p[0]=e0*inv; p[1]=e1*inv; p[2]=e2*inv; p[3]=e3*inv;
    }
}

// ---------------- expert-preferred greedy assignment + expert-sort permutation ----------------
__global__ void assign_kernel() {
    __shared__ unsigned long long keys[NN];
    __shared__ int asg[NN];
    int b = blockIdx.x;
    int t = threadIdx.x;
    for (int i = t; i < NN; i += 1024) asg[i] = -1;
    const int caps[EE] = {1024, 512, 256, 256};
    for (int e = EE-1; e >= 1; e--) {
        __syncthreads();
        for (int i = t; i < NN; i += 1024) {
            unsigned pb = __float_as_uint(g_probs[((size_t)b*NN+i)*EE + e]);
            unsigned long long key =
                ((unsigned long long)(asg[i] < 0 ? 1u : 0u) << 63) |
                ((unsigned long long)pb << 16) |
                (unsigned long long)(NN-1-i);
            keys[i] = key;
        }
        __syncthreads();
        for (int k = 2; k <= NN; k <<= 1) {
            for (int j = k >> 1; j > 0; j >>= 1) {
                for (int ii = t; ii < NN; ii += 1024) {
                    int l = ii ^ j;
                    if (l > ii) {
                        unsigned long long va = keys[ii], vb = keys[l];
                        bool desc = ((ii & k) == 0);
                        if (desc ? (va < vb) : (va > vb)) { keys[ii]=vb; keys[l]=va; }
                    }
                }
                __syncthreads();
            }
        }
        int cap = caps[e];
        for (int i = t; i < cap; i += 1024) {
            int idx = NN-1 - (int)(keys[i] & 0xffffu);
            asg[idx] = e;
        }
    }
    __syncthreads();
    for (int i = t; i < NN; i += 1024) {
        int a = asg[i]; if (a < 0) a = 0;
        asg[i] = a;
        g_assigned[b*NN+i] = a;
        g_rp[b*NN+i] = g_probs[((size_t)b*NN+i)*EE + a];
    }
    __syncthreads();
    // final sort: expert desc, token idx asc -> permutation with fixed segments
    for (int i = t; i < NN; i += 1024)
        keys[i] = ((unsigned long long)asg[i] << 16) | (unsigned long long)(NN-1-i);
    __syncthreads();
    for (int k = 2; k <= NN; k <<= 1) {
        for (int j = k >> 1; j > 0; j >>= 1) {
            for (int ii = t; ii < NN; ii += 1024) {
                int l = ii ^ j;
                if (l > ii) {
                    unsigned long long va = keys[ii], vb = keys[l];
                    bool desc = ((ii & k) == 0);
                    if (desc ? (va < vb) : (va > vb)) { keys[ii]=vb; keys[l]=va; }
                }
            }
            __syncthreads();
        }
    }
    for (int j = t; j < NN; j += 1024) {
        int idx = NN-1 - (int)(keys[j] & 0xffffu);
        g_perm[b*NN + j] = b*NN + idx;
        g_rp_p[b*NN + j] = g_probs[((size_t)b*NN+idx)*EE + asg[idx]];
    }
}

// ---------------- weight transpose + split-bf16 convert: Wt[n][k] = W[k][n] ----------------
template<int MODE>
__global__ void wconv_kernel(const float* __restrict__ W) {
    constexpr int K = (MODE==3)?2048:512;
    constexpr int N = (MODE==0)?1536:(MODE==2)?2048:512;
    __nv_bfloat16* oh = (MODE==0)?g_wqkvT_h:(MODE==1)?g_woT_h:(MODE==2)?g_w1T_h:g_w2T_h;
    __nv_bfloat16* ol = (MODE==0)?g_wqkvT_l:(MODE==1)?g_woT_l:(MODE==2)?g_w1T_l:g_w2T_l;
    __shared__ float tbuf[32][33];
    int n0 = blockIdx.x*32, k0 = blockIdx.y*32;
    int tx = threadIdx.x, ty = threadIdx.y;
    #pragma unroll
    for (int i = 0; i < 4; i++)
        tbuf[ty+i*8][tx] = W[(size_t)(k0+ty+i*8)*N + n0+tx];
    __syncthreads();
    #pragma unroll
    for (int i = 0; i < 4; i++) {
        int n = n0 + ty + i*8, k = k0 + tx;
        float v = tbuf[tx][ty+i*8];
        __nv_bfloat16 h, l; bf16_split(v, h, l);
        oh[(size_t)n*K + k] = h;
        ol[(size_t)n*K + k] = l;
    }
}

// ---------------- layernorm + feature mask -> split bf16 (permuted rows) ----------------
template<int LM>
__global__ void ln_mask_kernel(const float* __restrict__ xin,
                               const float* __restrict__ g,
                               const float* __restrict__ be) {
    int tok = blockIdx.x;     // permuted row
    int t = threadIdx.x;      // 128
    __nv_bfloat16* oh = (LM == 0) ? g_h_h : g_hm_h;
    __nv_bfloat16* ol = (LM == 0) ? g_h_l : g_hm_l;
    const float* xr;
    if (LM == 0) xr = xin + (size_t)g_perm[tok] * DD;
    else         xr = g_z + (size_t)tok * DD;
    float v[4]; float s = 0.f;
    #pragma unroll
    for (int i = 0; i < 4; i++) { v[i] = xr[t + 128*i]; s += v[i]; }
    __shared__ float red[4];
    for (int o = 16; o; o >>= 1) s += __shfl_xor_sync(0xffffffffu, s, o);
    if ((t & 31) == 0) red[t >> 5] = s;
    __syncthreads();
    float mu = (red[0]+red[1]+red[2]+red[3]) * (1.f/DD);
    float s2 = 0.f;
    #pragma unroll
    for (int i = 0; i < 4; i++) { float d = v[i]-mu; s2 += d*d; }
    __syncthreads();
    for (int o = 16; o; o >>= 1) s2 += __shfl_xor_sync(0xffffffffu, s2, o);
    if ((t & 31) == 0) red[t >> 5] = s2;
    __syncthreads();
    float var = (red[0]+red[1]+red[2]+red[3]) * (1.f/DD);
    float rs = rsqrtf(var + 1e-5f);
    int dt = dt_of_rank(tok & (NN-1));
    #pragma unroll
    for (int i = 0; i < 4; i++) {
        int c = t + 128*i;
        float val = (c < dt) ? ((v[i]-mu)*rs*g[c] + be[c]) : 0.f;
        __nv_bfloat16 h, l; bf16_split(val, h, l);
        oh[(size_t)tok*DD + c] = h;
        ol[(size_t)tok*DD + c] = l;
    }
}

__device__ __forceinline__ float gelu_f(float x) {
    float x3 = x*x*x;
    return 0.5f * x * (1.f + tanhf(0.7978845608028654f * (x + 0.044715f * x3)));
}

// ---------------- HMMA split-bf16 GEMM: 128x128 CTA tile, sparsity-aware ----------------
#define PITCH 40
template<int MODE>
__global__ __launch_bounds__(256)
void tgemm_kernel(const float* __restrict__ bias,
                  const float* __restrict__ xin,
                  const float* __restrict__ alpha,
                  float* __restrict__ dout) {
    constexpr int KT  = (MODE == 3) ? 2048 : 512;
    const __nv_bfloat16* Ahg = (MODE==0)?g_h_h:(MODE==1)?g_o_h:(MODE==2)?g_hm_h:g_hid_h;
    const __nv_bfloat16* Alg = (MODE==0)?g_h_l:(MODE==1)?g_o_l:(MODE==2)?g_hm_l:g_hid_l;
    const __nv_bfloat16* Bhg = (MODE==0)?g_wqkvT_h:(MODE==1)?g_woT_h:(MODE==2)?g_w1T_h:g_w2T_h;
    const __nv_bfloat16* Blg = (MODE==0)?g_wqkvT_l:(MODE==1)?g_woT_l:(MODE==2)?g_w1T_l:g_w2T_l;
    extern __shared__ __nv_bfloat16 sm[];
    __nv_bfloat16* sAh = sm;
    __nv_bfloat16* sAl = sm + 128*PITCH;
    __nv_bfloat16* sBh = sm + 2*128*PITCH;
    __nv_bfloat16* sBl = sm + 3*128*PITCH;
    int tid = threadIdx.x;
    int lane = tid & 31, w = tid >> 5;
    int wm = w & 1, wn = w >> 1;
    int m0 = blockIdx.y * 128;
    int n0 = blockIdx.x * 128;
    int dt = dt_of_rank(m0 & (NN-1));   // tile-homogeneous after expert sort

    // sparsity guards
    if (MODE == 2 && n0 >= 4*dt) return;   // never read downstream
    bool run_main;
    if      (MODE == 0) run_main = ((n0 & 511) < dt);
    else if (MODE == 1) run_main = (n0 < dt);
    else if (MODE == 2) run_main = true;
    else                run_main = (n0 < dt);
    int nch;  // live K chunks of 32
    if (MODE == 3) nch = dt >> 3;   // 4*dt/32
    else           nch = dt >> 5;

    float acc[4][4][4] = {};

    if (run_main) {
        int lrow = tid >> 2, lq = tid & 3;
        const __nv_bfloat16* pAh = Ahg + (size_t)(m0 + lrow)*KT + lq*8;
        const __nv_bfloat16* pAl = Alg + (size_t)(m0 + lrow)*KT + lq*8;
        const __nv_bfloat16* pBh = Bhg + (size_t)(n0 + lrow)*KT + lq*8;
        const __nv_bfloat16* pBl = Blg + (size_t)(n0 + lrow)*KT + lq*8;
        uint32_t soff0 = lrow*PITCH + lq*8;
        uint32_t soff1 = (lrow + 64)*PITCH + lq*8;

        uint32_t sb = smem_u32(sm);
        uint32_t aoffH = sb + ((wm*64 + (lane & 15))*PITCH + (lane >> 4)*8)*2;
        uint32_t aoffL = aoffH + 128*PITCH*2;
        uint32_t boffH = sb + 2*128*PITCH*2 + ((wn*32 + (lane & 7))*PITCH + ((lane >> 3) & 1)*8)*2;
        uint32_t boffL = boffH + 128*PITCH*2;

        for (int c = 0; c < nch; c++) {
            size_t go = (size_t)c * 32;
            *(uint4*)(sAh + soff0) = *(const uint4*)(pAh + go);
            *(uint4*)(sAh + soff1) = *(const uint4*)(pAh + go + (size_t)64*KT);
            *(uint4*)(sAl + soff0) = *(const uint4*)(pAl + go);
            *(uint4*)(sAl + soff1) = *(const uint4*)(pAl + go + (size_t)64*KT);
            *(uint4*)(sBh + soff0) = *(const uint4*)(pBh + go);
            *(uint4*)(sBh + soff1) = *(const uint4*)(pBh + go + (size_t)64*KT);
            *(uint4*)(sBl + soff0) = *(const uint4*)(pBl + go);
            *(uint4*)(sBl + soff1) = *(const uint4*)(pBl + go + (size_t)64*KT);
            __syncthreads();
            #pragma unroll
            for (int kk = 0; kk < 2; kk++) {
                uint32_t ah[4][4], al[4][4], bh[4][2], bl[4][2];
                #pragma unroll
                for (int mt = 0; mt < 4; mt++) {
                    ldsm_x4(ah[mt], aoffH + (mt*16*PITCH + kk*16)*2);
                    ldsm_x4(al[mt], aoffL + (mt*16*PITCH + kk*16)*2);
                }
                #pragma unroll
                for (int nt = 0; nt < 4; nt++) {
                    ldsm_x2(bh[nt], boffH + (nt*8*PITCH + kk*16)*2);
                    ldsm_x2(bl[nt], boffL + (nt*8*PITCH + kk*16)*2);
                }
                #pragma unroll
                for (int mt = 0; mt < 4; mt++)
                    #pragma unroll
                    for (int nt = 0; nt < 4; nt++) {
                        mma16816(acc[mt][nt], ah[mt], bh[nt]);
                        mma16816(acc[mt][nt], ah[mt], bl[nt]);
                        mma16816(acc[mt][nt], al[mt], bh[nt]);
                    }
            }
            __syncthreads();
        }
    }

    float a0 = (MODE == 3) ? alpha[0] : 0.f;
    #pragma unroll
    for (int mt = 0; mt < 4; mt++) {
        #pragma unroll
        for (int p = 0; p < 2; p++) {
            int row = m0 + wm*64 + mt*16 + (lane >> 2) + p*8;
            float gate = (MODE == 3) ? (a0 * g_rp_p[row] + 1.f) : 0.f;
            int prow = (MODE == 1 || MODE == 3) ? g_perm[row] : 0;
            #pragma unroll
            for (int nt = 0; nt < 4; nt++) {
                #pragma unroll
                for (int e = 0; e < 2; e++) {
                    int c2 = n0 + wn*32 + nt*8 + (lane & 3)*2 + e;
                    float v = acc[mt][nt][p*2 + e];
                    if constexpr (MODE == 0) {
                        int cc = c2 & 511;
                        v = (cc < dt) ? v : 0.f;
                        int sel = c2 >> 9;
                        int hh = cc >> 6, dd = cc & 63;
                        int bidx = row >> 11, n = row & (NN-1);
                        uint32_t* dst = (sel == 0) ? g_q_p : (sel == 1) ? g_k_p : g_v_p;
                        dst[(((size_t)(bidx*HH + hh))*NN + n)*64 + dd] = pack_split(v);
                    } else if constexpr (MODE == 1) {
                        v += bias[c2];
                        v = (c2 < dt) ? v : 0.f;
                        g_z[(size_t)row*DD + c2] = xin[(size_t)prow*DD + c2] + v;
                    } else if constexpr (MODE == 2) {
                        v += bias[c2];
                        v = (c2 < 4*dt) ? v : 0.f;
                        float gv = gelu_f(v);
                        __nv_bfloat16 h, l; bf16_split(gv, h, l);
                        g_hid_h[(size_t)row*RD + c2] = h;
                        g_hid_l[(size_t)row*RD + c2] = l;
                    } else {
                        v += bias[c2];
                        v = (c2 < dt) ? v : 0.f;
                        dout[(size_t)prow*DD + c2] = g_z[(size_t)row*DD + c2] + gate * v;
                    }
                }
            }
        }
    }
}

// ---------------- HMMA flash attention, head-level query skipping ----------------
#define APITCH 72
__global__ __launch_bounds__(256)
void attn_kernel() {
    __shared__ uint16_t smH[128*APITCH];
    __shared__ uint16_t smL[128*APITCH];
    int bh = blockIdx.y;
    int b = bh >> 3;
    int h = bh & 7;
    int m0 = blockIdx.x * 128;         // rank within batch
    int tid = threadIdx.x;
    int lane = tid & 31, w = tid >> 5;
    int dtq = dt_of_rank(m0);          // query tile homogeneous

    if (h*64 >= dtq) {
        // whole head masked for these query rows: write zeros, done
        for (int i = tid; i < 128*64; i += 256) {
            int r = i >> 6, f = i & 63;
            size_t off = (size_t)(b*NN + m0 + r)*DD + h*64 + f;
            g_o_h[off] = __float2bfloat16(0.f);
            g_o_l[off] = __float2bfloat16(0.f);
        }
        return;
    }

    const uint32_t* qp = g_q_p + (size_t)bh * NN * 64;
    const uint32_t* kp = g_k_p + (size_t)bh * NN * 64;
    const uint32_t* vp = g_v_p + (size_t)bh * NN * 64;

    // ---- fill Q tile ----
    {
        int row = tid >> 1, hb = (tid & 1) * 32;
        const uint4* src = (const uint4*)(qp + (size_t)(m0 + row)*64 + hb);
        #pragma unroll
        for (int j = 0; j < 8; j++) {
            uint4 u = src[j];
            uint32_t ws[4] = {u.x, u.y, u.z, u.w};
            #pragma unroll
            for (int q = 0; q < 4; q++) {
                int d = hb + j*4 + q;
                smH[row*APITCH + d] = (uint16_t)(ws[q] & 0xFFFFu);
                smL[row*APITCH + d] = (uint16_t)(ws[q] >> 16);
            }
        }
    }
    __syncthreads();
    uint32_t qa_h[4][4], qa_l[4][4];
    {
        uint32_t qoffH = smem_u32(smH) + ((w*16 + (lane & 15))*APITCH + (lane >> 4)*8)*2;
        uint32_t qoffL = smem_u32(smL) + ((w*16 + (lane & 15))*APITCH + (lane >> 4)*8)*2;
        #pragma unroll
        for (int kc = 0; kc < 4; kc++) {
            ldsm_x4(qa_h[kc], qoffH + kc*16*2);
            ldsm_x4(qa_l[kc], qoffL + kc*16*2);
        }
    }
    __syncthreads();

    uint32_t kbH = smem_u32(smH) + ((lane & 7)*APITCH + ((lane >> 3) & 1)*8)*2;
    uint32_t kbL = smem_u32(smL) + ((lane & 7)*APITCH + ((lane >> 3) & 1)*8)*2;
    uint32_t vbH = smem_u32(smH) + ((64 + (lane & 7))*APITCH + ((lane >> 3) & 1)*8)*2;
    uint32_t vbL = smem_u32(smL) + ((64 + (lane & 7))*APITCH + ((lane >> 3) & 1)*8)*2;

    float O[8][4] = {};
    float mold0 = -1e30f, mold1 = -1e30f, lsum0 = 0.f, lsum1 = 0.f;

    for (int n0 = 0; n0 < NN; n0 += 64) {
        {
            int key = tid >> 2, part = (tid & 3)*16;
            const uint4* src = (const uint4*)(kp + (size_t)(n0 + key)*64 + part);
            #pragma unroll
            for (int j = 0; j < 4; j++) {
                uint4 u = src[j];
                uint32_t ws[4] = {u.x, u.y, u.z, u.w};
                #pragma unroll
                for (int q = 0; q < 4; q++) {
                    int d = part + j*4 + q;
                    smH[key*APITCH + d] = (uint16_t)(ws[q] & 0xFFFFu);
                    smL[key*APITCH + d] = (uint16_t)(ws[q] >> 16);
                }
            }
        }
        {
            int key = tid & 63, dbase = (tid >> 6)*16;
            const uint4* src = (const uint4*)(vp + (size_t)(n0 + key)*64 + dbase);
            #pragma unroll
            for (int j = 0; j < 4; j++) {
                uint4 u = src[j];
                uint32_t ws[4] = {u.x, u.y, u.z, u.w};
                #pragma unroll
                for (int q = 0; q < 4; q++) {
                    int d = dbase + j*4 + q;
                    smH[(64 + d)*APITCH + key] = (uint16_t)(ws[q] & 0xFFFFu);
                    smL[(64 + d)*APITCH + key] = (uint16_t)(ws[q] >> 16);
                }
            }
        }
        __syncthreads();

        float S[8][4] = {};
        #pragma unroll
        for (int kc = 0; kc < 4; kc++) {
            #pragma unroll
            for (int nt = 0; nt < 8; nt++) {
                uint32_t kb2[2], kl2[2];
                ldsm_x2(kb2, kbH + (nt*8*APITCH + kc*16)*2);
                ldsm_x2(kl2, kbL + (nt*8*APITCH + kc*16)*2);
                mma16816(S[nt], qa_h[kc], kb2);
                mma16816(S[nt], qa_h[kc], kl2);
                mma16816(S[nt], qa_l[kc], kb2);
            }
        }
        float mx0 = -1e30f, mx1 = -1e30f;
        #pragma unroll
        for (int nt = 0; nt < 8; nt++) {
            S[nt][0] *= 0.125f; S[nt][1] *= 0.125f; S[nt][2] *= 0.125f; S[nt][3] *= 0.125f;
            mx0 = fmaxf(mx0, fmaxf(S[nt][0], S[nt][1]));
            mx1 = fmaxf(mx1, fmaxf(S[nt][2], S[nt][3]));
        }
        mx0 = fmaxf(mx0, __shfl_xor_sync(0xffffffffu, mx0, 1));
        mx0 = fmaxf(mx0, __shfl_xor_sync(0xffffffffu, mx0, 2));
        mx1 = fmaxf(mx1, __shfl_xor_sync(0xffffffffu, mx1, 1));
        mx1 = fmaxf(mx1, __shfl_xor_sync(0xffffffffu, mx1, 2));
        float mn0 = fmaxf(mold0, mx0), mn1 = fmaxf(mold1, mx1);
        float corr0 = fast_exp(mold0 - mn0), corr1 = fast_exp(mold1 - mn1);
        float rs0 = 0.f, rs1 = 0.f;
        #pragma unroll
        for (int nt = 0; nt < 8; nt++) {
            S[nt][0] = fast_exp(S[nt][0] - mn0); rs0 += S[nt][0];
            S[nt][1] = fast_exp(S[nt][1] - mn0); rs0 += S[nt][1];
            S[nt][2] = fast_exp(S[nt][2] - mn1); rs1 += S[nt][2];
            S[nt][3] = fast_exp(S[nt][3] - mn1); rs1 += S[nt][3];
        }
        rs0 += __shfl_xor_sync(0xffffffffu, rs0, 1);
        rs0 += __shfl_xor_sync(0xffffffffu, rs0, 2);
        rs1 += __shfl_xor_sync(0xffffffffu, rs1, 1);
        rs1 += __shfl_xor_sync(0xffffffffu, rs1, 2);
        lsum0 = lsum0*corr0 + rs0;
        lsum1 = lsum1*corr1 + rs1;
        #pragma unroll
        for (int nt = 0; nt < 8; nt++) {
            O[nt][0] *= corr0; O[nt][1] *= corr0; O[nt][2] *= corr1; O[nt][3] *= corr1;
        }
        mold0 = mn0; mold1 = mn1;

        #pragma unroll
        for (int kc = 0; kc < 4; kc++) {
            uint32_t pah[4], pal[4];
            #pragma unroll
            for (int half = 0; half < 2; half++) {
                int nt = 2*kc + half;
                __nv_bfloat16 h0,l0,h1,l1,h2,l2,h3,l3;
                bf16_split(S[nt][0], h0, l0);
                bf16_split(S[nt][1], h1, l1);
                bf16_split(S[nt][2], h2, l2);
                bf16_split(S[nt][3], h3, l3);
                pah[half*2+0] = (uint32_t)__bfloat16_as_ushort(h0) | ((uint32_t)__bfloat16_as_ushort(h1) << 16);
                pah[half*2+1] = (uint32_t)__bfloat16_as_ushort(h2) | ((uint32_t)__bfloat16_as_ushort(h3) << 16);
                pal[half*2+0] = (uint32_t)__bfloat16_as_ushort(l0) | ((uint32_t)__bfloat16_as_ushort(l1) << 16);
                pal[half*2+1] = (uint32_t)__bfloat16_as_ushort(l2) | ((uint32_t)__bfloat16_as_ushort(l3) << 16);
            }
            #pragma unroll
            for (int nt = 0; nt < 8; nt++) {
                uint32_t vh2[2], vl2[2];
                ldsm_x2(vh2, vbH + (nt*8*APITCH + kc*16)*2);
                ldsm_x2(vl2, vbL + (nt*8*APITCH + kc*16)*2);
                mma16816(O[nt], pah, vh2);
                mma16816(O[nt], pah, vl2);
                mma16816(O[nt], pal, vh2);
            }
        }
        __syncthreads();
    }

    float inv0 = 1.f / lsum0, inv1 = 1.f / lsum1;
    int r0 = m0 + w*16 + (lane >> 2);
    int row0 = b*NN + r0, row1 = row0 + 8;
    #pragma unroll
    for (int nt = 0; nt < 8; nt++) {
        #pragma unroll
        for (int e = 0; e < 2; e++) {
            int feat = h*64 + nt*8 + (lane & 3)*2 + e;
            float v0 = O[nt][e]*inv0;       // head fully active (feat < dtq guaranteed)
            float v1 = O[nt][2+e]*inv1;
            __nv_bfloat16 hh, ll;
            bf16_split(v0, hh, ll);
            g_o_h[(size_t)row0*DD + feat] = hh;
            g_o_l[(size_t)row0*DD + feat] = ll;
            bf16_split(v1, hh, ll);
            g_o_h[(size_t)row1*DD + feat] = hh;
            g_o_l[(size_t)row1*DD + feat] = ll;
        }
    }
}

// extra outputs (assigned, rp) — token space, reference returns the full tuple
__global__ void extras_kernel(float* dout, int out_size) {
    int i = blockIdx.x * blockDim.x + threadIdx.x;
    if (i >= MROWS) return;
    const int base = MROWS*DD;
    if (out_size >= base + MROWS)   dout[base + i] = (float)g_assigned[i];
    if (out_size >= base + 2*MROWS) dout[base + MROWS + i] = g_rp[i];
}

extern "C" void kernel_launch(void* const* d_in, const int* in_sizes, int n_in,
                              void* d_out, int out_size) {
    const float* x    = (const float*)d_in[0];
    const float* r_w  = (const float*)d_in[1];
    const float* r_b  = (const float*)d_in[2];
    const float* g1   = (const float*)d_in[3];
    const float* b1   = (const float*)d_in[4];
    const float* g2   = (const float*)d_in[5];
    const float* b2   = (const float*)d_in[6];
    const float* wqkv = (const float*)d_in[7];
    const float* wo   = (const float*)d_in[8];
    const float* bo   = (const float*)d_in[9];
    const float* w1   = (const float*)d_in[10];
    const float* b1f  = (const float*)d_in[11];
    const float* w2   = (const float*)d_in[12];
    const float* b2f  = (const float*)d_in[13];
    const float* alpha= (const float*)d_in[14];
    float* out = (float*)d_out;

    constexpr int TG_SMEM = 4 * 128 * PITCH * 2;  // 40960 B

    router_kernel<<<MROWS/4, 128>>>(x, r_w, r_b);
    assign_kernel<<<BB, 1024>>>();
    wconv_kernel<0><<<dim3(1536/32, 512/32),  dim3(32,8)>>>(wqkv);
    wconv_kernel<1><<<dim3(512/32,  512/32),  dim3(32,8)>>>(wo);
    wconv_kernel<2><<<dim3(2048/32, 512/32),  dim3(32,8)>>>(w1);
    wconv_kernel<3><<<dim3(512/32,  2048/32), dim3(32,8)>>>(w2);
    ln_mask_kernel<0><<<MROWS, 128>>>(x, g1, b1);
    tgemm_kernel<0><<<dim3(1536/128, MROWS/128), 256, TG_SMEM>>>(nullptr, nullptr, nullptr, nullptr);
    attn_kernel<<<dim3(NN/128, BB*HH), 256>>>();
    tgemm_kernel<1><<<dim3(512/128, MROWS/128), 256, TG_SMEM>>>(bo, x, nullptr, nullptr);
    ln_mask_kernel<1><<<MROWS, 128>>>(nullptr, g2, b2);
    tgemm_kernel<2><<<dim3(2048/128, MROWS/128), 256, TG_SMEM>>>(b1f, nullptr, nullptr, nullptr);
    tgemm_kernel<3><<<dim3(512/128, MROWS/128), 256, TG_SMEM>>>(b2f, nullptr, alpha, out);
    if (out_size > MROWS*DD)
        extras_kernel<<<(MROWS+255)/256, 256>>>(out, out_size);
}

// round 15
// speedup vs baseline: 4.5682x; 1.3054x over previous
#include <cuda_runtime.h>
#include <cuda_bf16.h>
#include <math.h>
#include <stdint.h>

#define BB 4
#define NN 2048
#define DD 512
#define HH 8
#define EE 4
#define RD 2048
#define MROWS (BB*NN)

// ---------------- scratch (device globals: no runtime allocation) ----------------
__device__ float g_probs[MROWS*EE];
__device__ int   g_assigned[MROWS];
__device__ float g_rp[MROWS];
__device__ int   g_perm[MROWS];      // rank -> global token index
__device__ float g_rp_p[MROWS];      // router prob at permuted rows
__device__ float g_z[MROWS*DD];      // permuted rows
// packed split-bf16 q/k/v: word = bits(hi) | bits(lo)<<16, layout [bh][rank][64]
__device__ uint32_t g_q_p[MROWS*DD];
__device__ uint32_t g_k_p[MROWS*DD];
__device__ uint32_t g_v_p[MROWS*DD];
// split-bf16 activations (hi/lo), permuted rows
__device__ __nv_bfloat16 g_h_h[MROWS*DD],  g_h_l[MROWS*DD];
__device__ __nv_bfloat16 g_o_h[MROWS*DD],  g_o_l[MROWS*DD];
__device__ __nv_bfloat16 g_hm_h[MROWS*DD], g_hm_l[MROWS*DD];
__device__ __nv_bfloat16 g_hid_h[(size_t)MROWS*RD], g_hid_l[(size_t)MROWS*RD];
// transposed split-bf16 weights  Wt[n][k]
__device__ __nv_bfloat16 g_wqkvT_h[1536*512], g_wqkvT_l[1536*512];
__device__ __nv_bfloat16 g_woT_h[512*512],    g_woT_l[512*512];
__device__ __nv_bfloat16 g_w1T_h[2048*512],   g_w1T_l[2048*512];
__device__ __nv_bfloat16 g_w2T_h[512*2048],   g_w2T_l[512*2048];

// segments per batch after sort: [0,256)->512, [256,512)->256, [512,1024)->128, [1024,2048)->64
__device__ __forceinline__ int dt_of_rank(int rr) {
    return (rr < 256) ? 512 : (rr < 512) ? 256 : (rr < 1024) ? 128 : 64;
}

// ---------------- PTX helpers (baseline ISA only: ldmatrix + mma.sync) ----------------
__device__ __forceinline__ uint32_t smem_u32(const void* p) {
    uint32_t a;
    asm("{ .reg .u64 t; cvta.to.shared.u64 t, %1; cvt.u32.u64 %0, t; }" : "=r"(a) : "l"(p));
    return a;
}
__device__ __forceinline__ void ldsm_x4(uint32_t* r, uint32_t addr) {
    asm volatile("ldmatrix.sync.aligned.m8n8.x4.shared.b16 {%0,%1,%2,%3}, [%4];"
                 : "=r"(r[0]), "=r"(r[1]), "=r"(r[2]), "=r"(r[3]) : "r"(addr));
}
__device__ __forceinline__ void ldsm_x2(uint32_t* r, uint32_t addr) {
    asm volatile("ldmatrix.sync.aligned.m8n8.x2.shared.b16 {%0,%1}, [%2];"
                 : "=r"(r[0]), "=r"(r[1]) : "r"(addr));
}
__device__ __forceinline__ void mma16816(float* c, const uint32_t* a, const uint32_t* b) {
    asm volatile(
        "mma.sync.aligned.m16n8k16.row.col.f32.bf16.bf16.f32 "
        "{%0,%1,%2,%3}, {%4,%5,%6,%7}, {%8,%9}, {%0,%1,%2,%3};"
        : "+f"(c[0]), "+f"(c[1]), "+f"(c[2]), "+f"(c[3])
        : "r"(a[0]), "r"(a[1]), "r"(a[2]), "r"(a[3]), "r"(b[0]), "r"(b[1]));
}
__device__ __forceinline__ void bf16_split(float v, __nv_bfloat16& h, __nv_bfloat16& l) {
    h = __float2bfloat16(v);
    l = __float2bfloat16(v - __bfloat162float(h));
}
__device__ __forceinline__ uint32_t pack_split(float v) {
    __nv_bfloat16 h, l; bf16_split(v, h, l);
    return (uint32_t)__bfloat16_as_ushort(h) | ((uint32_t)__bfloat16_as_ushort(l) << 16);
}
// fast exp on fma pipe (no MUFU)
__device__ __forceinline__ float fast_exp(float x) {
    x = fmaxf(x, -87.0f);
    float t = x * 1.4426950408889634f;
    float r = rintf(t);
    float f = t - r;
    float p = 1.5403530393381609e-4f;
    p = fmaf(p, f, 1.3333558146428443e-3f);
    p = fmaf(p, f, 9.6181291076284772e-3f);
    p = fmaf(p, f, 5.5504108664821580e-2f);
    p = fmaf(p, f, 2.4022650695910071e-1f);
    p = fmaf(p, f, 6.9314718055994531e-1f);
    p = fmaf(p, f, 1.0f);
    int i = (int)r;
    return p * __int_as_float((i + 127) << 23);
}

// ---------------- router: logits + softmax ----------------
__global__ void router_kernel(const float* __restrict__ x,
                              const float* __restrict__ rw,
                              const float* __restrict__ rb) {
    int gw = (blockIdx.x * blockDim.x + threadIdx.x) >> 5;
    int lane = threadIdx.x & 31;
    if (gw >= MROWS) return;
    const float* xr = x + (size_t)gw * DD;
    float a0=0.f,a1=0.f,a2=0.f,a3=0.f;
    for (int k = lane; k < DD; k += 32) {
        float xv = xr[k];
        const float* w = rw + (size_t)k*EE;
        a0 += xv*w[0]; a1 += xv*w[1]; a2 += xv*w[2]; a3 += xv*w[3];
    }
    for (int o = 16; o; o >>= 1) {
        a0 += __shfl_xor_sync(0xffffffffu, a0, o);
        a1 += __shfl_xor_sync(0xffffffffu, a1, o);
        a2 += __shfl_xor_sync(0xffffffffu, a2, o);
        a3 += __shfl_xor_sync(0xffffffffu, a3, o);
    }
    if (lane == 0) {
        float l0=a0+rb[0], l1=a1+rb[1], l2=a2+rb[2], l3=a3+rb[3];
        float mx = fmaxf(fmaxf(l0,l1), fmaxf(l2,l3));
        float e0=expf(l0-mx), e1=expf(l1-mx), e2=expf(l2-mx), e3=expf(l3-mx);
        float inv = 1.f/(e0+e1+e2+e3);
        float* p = g_probs + (size_t)gw*EE;
        p[0]=e0*inv; p[1]=e1*inv; p[2]=e2*inv; p[3]=e3*inv;
    }
}

// ---------------- expert-preferred greedy assignment + counting permutation ----------------
__global__ void assign_kernel() {
    __shared__ unsigned long long keys[NN];
    __shared__ int asg[NN];
    __shared__ uint32_t emask[4][64];
    __shared__ int epref[4][64];
    int b = blockIdx.x;
    int t = threadIdx.x;
    for (int i = t; i < NN; i += 1024) asg[i] = -1;
    const int caps[EE] = {1024, 512, 256, 256};
    for (int e = EE-1; e >= 1; e--) {
        __syncthreads();
        for (int i = t; i < NN; i += 1024) {
            unsigned pb = __float_as_uint(g_probs[((size_t)b*NN+i)*EE + e]);
            unsigned long long key =
                ((unsigned long long)(asg[i] < 0 ? 1u : 0u) << 63) |
                ((unsigned long long)pb << 16) |
                (unsigned long long)(NN-1-i);
            keys[i] = key;
        }
        __syncthreads();
        for (int k = 2; k <= NN; k <<= 1) {
            for (int j = k >> 1; j > 0; j >>= 1) {
                for (int ii = t; ii < NN; ii += 1024) {
                    int l = ii ^ j;
                    if (l > ii) {
                        unsigned long long va = keys[ii], vb = keys[l];
                        bool desc = ((ii & k) == 0);
                        if (desc ? (va < vb) : (va > vb)) { keys[ii]=vb; keys[l]=va; }
                    }
                }
                __syncthreads();
            }
        }
        int cap = caps[e];
        for (int i = t; i < cap; i += 1024) {
            int idx = NN-1 - (int)(keys[i] & 0xffffu);
            asg[idx] = e;
        }
    }
    __syncthreads();
    for (int i = t; i < NN; i += 1024) {
        int a = asg[i]; if (a < 0) a = 0;
        asg[i] = a;
        g_assigned[b*NN+i] = a;
        g_rp[b*NN+i] = g_probs[((size_t)b*NN+i)*EE + a];
    }
    // counting-based stable partition (expert desc, idx asc) -> permutation
    for (int i = t; i < 4*64; i += 1024) ((uint32_t*)emask)[i] = 0;
    __syncthreads();
    for (int i = t; i < NN; i += 1024)
        atomicOr(&emask[asg[i]][i >> 5], 1u << (i & 31));
    __syncthreads();
    if (t < 4) {
        int s = 0;
        for (int wd = 0; wd < 64; wd++) { epref[t][wd] = s; s += __popc(emask[t][wd]); }
    }
    __syncthreads();
    const int base[4] = {1024, 512, 256, 0};
    for (int i = t; i < NN; i += 1024) {
        int e = asg[i];
        int wd = i >> 5, bit = i & 31;
        int r = base[e] + epref[e][wd] + __popc(emask[e][wd] & ((1u << bit) - 1u));
        g_perm[b*NN + r] = b*NN + i;
        g_rp_p[b*NN + r] = g_probs[((size_t)b*NN+i)*EE + e];
    }
}

// ---------------- weight transpose + split-bf16 convert: Wt[n][k] = W[k][n] ----------------
template<int MODE>
__global__ void wconv_kernel(const float* __restrict__ W) {
    constexpr int K = (MODE==3)?2048:512;
    constexpr int N = (MODE==0)?1536:(MODE==2)?2048:512;
    __nv_bfloat16* oh = (MODE==0)?g_wqkvT_h:(MODE==1)?g_woT_h:(MODE==2)?g_w1T_h:g_w2T_h;
    __nv_bfloat16* ol = (MODE==0)?g_wqkvT_l:(MODE==1)?g_woT_l:(MODE==2)?g_w1T_l:g_w2T_l;
    __shared__ float tbuf[32][33];
    int n0 = blockIdx.x*32, k0 = blockIdx.y*32;
    int tx = threadIdx.x, ty = threadIdx.y;
    #pragma unroll
    for (int i = 0; i < 4; i++)
        tbuf[ty+i*8][tx] = W[(size_t)(k0+ty+i*8)*N + n0+tx];
    __syncthreads();
    #pragma unroll
    for (int i = 0; i < 4; i++) {
        int n = n0 + ty + i*8, k = k0 + tx;
        float v = tbuf[tx][ty+i*8];
        __nv_bfloat16 h, l; bf16_split(v, h, l);
        oh[(size_t)n*K + k] = h;
        ol[(size_t)n*K + k] = l;
    }
}

// ---------------- layernorm + feature mask -> split bf16 (permuted rows) ----------------
template<int LM>
__global__ void ln_mask_kernel(const float* __restrict__ xin,
                               const float* __restrict__ g,
                               const float* __restrict__ be) {
    int tok = blockIdx.x;     // permuted row
    int t = threadIdx.x;      // 128
    __nv_bfloat16* oh = (LM == 0) ? g_h_h : g_hm_h;
    __nv_bfloat16* ol = (LM == 0) ? g_h_l : g_hm_l;
    const float* xr;
    if (LM == 0) xr = xin + (size_t)g_perm[tok] * DD;
    else         xr = g_z + (size_t)tok * DD;
    float v[4]; float s = 0.f;
    #pragma unroll
    for (int i = 0; i < 4; i++) { v[i] = xr[t + 128*i]; s += v[i]; }
    __shared__ float red[4];
    for (int o = 16; o; o >>= 1) s += __shfl_xor_sync(0xffffffffu, s, o);
    if ((t & 31) == 0) red[t >> 5] = s;
    __syncthreads();
    float mu = (red[0]+red[1]+red[2]+red[3]) * (1.f/DD);
    float s2 = 0.f;
    #pragma unroll
    for (int i = 0; i < 4; i++) { float d = v[i]-mu; s2 += d*d; }
    __syncthreads();
    for (int o = 16; o; o >>= 1) s2 += __shfl_xor_sync(0xffffffffu, s2, o);
    if ((t & 31) == 0) red[t >> 5] = s2;
    __syncthreads();
    float var = (red[0]+red[1]+red[2]+red[3]) * (1.f/DD);
    float rs = rsqrtf(var + 1e-5f);
    int dt = dt_of_rank(tok & (NN-1));
    #pragma unroll
    for (int i = 0; i < 4; i++) {
        int c = t + 128*i;
        float val = (c < dt) ? ((v[i]-mu)*rs*g[c] + be[c]) : 0.f;
        __nv_bfloat16 h, l; bf16_split(val, h, l);
        oh[(size_t)tok*DD + c] = h;
        ol[(size_t)tok*DD + c] = l;
    }
}

__device__ __forceinline__ float gelu_f(float x) {
    float x3 = x*x*x;
    return 0.5f * x * (1.f + tanhf(0.7978845608028654f * (x + 0.044715f * x3)));
}

// ---------------- HMMA split-bf16 GEMM: 128x128 CTA tile, sparsity-aware ----------------
#define PITCH 40
template<int MODE>
__global__ __launch_bounds__(256)
void tgemm_kernel(const float* __restrict__ bias,
                  const float* __restrict__ xin,
                  const float* __restrict__ alpha,
                  float* __restrict__ dout) {
    constexpr int KT  = (MODE == 3) ? 2048 : 512;
    const __nv_bfloat16* Ahg = (MODE==0)?g_h_h:(MODE==1)?g_o_h:(MODE==2)?g_hm_h:g_hid_h;
    const __nv_bfloat16* Alg = (MODE==0)?g_h_l:(MODE==1)?g_o_l:(MODE==2)?g_hm_l:g_hid_l;
    const __nv_bfloat16* Bhg = (MODE==0)?g_wqkvT_h:(MODE==1)?g_woT_h:(MODE==2)?g_w1T_h:g_w2T_h;
    const __nv_bfloat16* Blg = (MODE==0)?g_wqkvT_l:(MODE==1)?g_woT_l:(MODE==2)?g_w1T_l:g_w2T_l;
    extern __shared__ __nv_bfloat16 sm[];
    __nv_bfloat16* sAh = sm;
    __nv_bfloat16* sAl = sm + 128*PITCH;
    __nv_bfloat16* sBh = sm + 2*128*PITCH;
    __nv_bfloat16* sBl = sm + 3*128*PITCH;
    int tid = threadIdx.x;
    int lane = tid & 31, w = tid >> 5;
    int wm = w & 1, wn = w >> 1;
    int m0 = blockIdx.y * 128;
    int n0 = blockIdx.x * 128;
    int dt = dt_of_rank(m0 & (NN-1));   // tile-homogeneous after expert sort

    // sparsity guards
    if (MODE == 2 && n0 >= 4*dt) return;   // never read downstream
    bool run_main;
    if      (MODE == 0) run_main = ((n0 & 511) < dt);
    else if (MODE == 1) run_main = (n0 < dt);
    else if (MODE == 2) run_main = true;
    else                run_main = (n0 < dt);
    int nch;  // live K chunks of 32
    if (MODE == 3) nch = dt >> 3;   // 4*dt/32
    else           nch = dt >> 5;

    float acc[4][4][4] = {};

    if (run_main) {
        int lrow = tid >> 2, lq = tid & 3;
        const __nv_bfloat16* pAh = Ahg + (size_t)(m0 + lrow)*KT + lq*8;
        const __nv_bfloat16* pAl = Alg + (size_t)(m0 + lrow)*KT + lq*8;
        const __nv_bfloat16* pBh = Bhg + (size_t)(n0 + lrow)*KT + lq*8;
        const __nv_bfloat16* pBl = Blg + (size_t)(n0 + lrow)*KT + lq*8;
        uint32_t soff0 = lrow*PITCH + lq*8;
        uint32_t soff1 = (lrow + 64)*PITCH + lq*8;

        uint32_t sb = smem_u32(sm);
        uint32_t aoffH = sb + ((wm*64 + (lane & 15))*PITCH + (lane >> 4)*8)*2;
        uint32_t aoffL = aoffH + 128*PITCH*2;
        uint32_t boffH = sb + 2*128*PITCH*2 + ((wn*32 + (lane & 7))*PITCH + ((lane >> 3) & 1)*8)*2;
        uint32_t boffL = boffH + 128*PITCH*2;

        for (int c = 0; c < nch; c++) {
            size_t go = (size_t)c * 32;
            *(uint4*)(sAh + soff0) = *(const uint4*)(pAh + go);
            *(uint4*)(sAh + soff1) = *(const uint4*)(pAh + go + (size_t)64*KT);
            *(uint4*)(sAl + soff0) = *(const uint4*)(pAl + go);
            *(uint4*)(sAl + soff1) = *(const uint4*)(pAl + go + (size_t)64*KT);
            *(uint4*)(sBh + soff0) = *(const uint4*)(pBh + go);
            *(uint4*)(sBh + soff1) = *(const uint4*)(pBh + go + (size_t)64*KT);
            *(uint4*)(sBl + soff0) = *(const uint4*)(pBl + go);
            *(uint4*)(sBl + soff1) = *(const uint4*)(pBl + go + (size_t)64*KT);
            __syncthreads();
            #pragma unroll
            for (int kk = 0; kk < 2; kk++) {
                uint32_t ah[4][4], al[4][4], bh[4][2], bl[4][2];
                #pragma unroll
                for (int mt = 0; mt < 4; mt++) {
                    ldsm_x4(ah[mt], aoffH + (mt*16*PITCH + kk*16)*2);
                    ldsm_x4(al[mt], aoffL + (mt*16*PITCH + kk*16)*2);
                }
                #pragma unroll
                for (int nt = 0; nt < 4; nt++) {
                    ldsm_x2(bh[nt], boffH + (nt*8*PITCH + kk*16)*2);
                    ldsm_x2(bl[nt], boffL + (nt*8*PITCH + kk*16)*2);
                }
                #pragma unroll
                for (int mt = 0; mt < 4; mt++)
                    #pragma unroll
                    for (int nt = 0; nt < 4; nt++) {
                        mma16816(acc[mt][nt], ah[mt], bh[nt]);
                        mma16816(acc[mt][nt], ah[mt], bl[nt]);
                        mma16816(acc[mt][nt], al[mt], bh[nt]);
                    }
            }
            __syncthreads();
        }
    }

    float a0 = (MODE == 3) ? alpha[0] : 0.f;
    #pragma unroll
    for (int mt = 0; mt < 4; mt++) {
        #pragma unroll
        for (int p = 0; p < 2; p++) {
            int row = m0 + wm*64 + mt*16 + (lane >> 2) + p*8;
            float gate = (MODE == 3) ? (a0 * g_rp_p[row] + 1.f) : 0.f;
            int prow = (MODE == 1 || MODE == 3) ? g_perm[row] : 0;
            #pragma unroll
            for (int nt = 0; nt < 4; nt++) {
                #pragma unroll
                for (int e = 0; e < 2; e++) {
                    int c2 = n0 + wn*32 + nt*8 + (lane & 3)*2 + e;
                    float v = acc[mt][nt][p*2 + e];
                    if constexpr (MODE == 0) {
                        int cc = c2 & 511;
                        v = (cc < dt) ? v : 0.f;
                        int sel = c2 >> 9;
                        int hh = cc >> 6, dd = cc & 63;
                        int bidx = row >> 11, n = row & (NN-1);
                        uint32_t* dst = (sel == 0) ? g_q_p : (sel == 1) ? g_k_p : g_v_p;
                        dst[(((size_t)(bidx*HH + hh))*NN + n)*64 + dd] = pack_split(v);
                    } else if constexpr (MODE == 1) {
                        v += bias[c2];
                        v = (c2 < dt) ? v : 0.f;
                        g_z[(size_t)row*DD + c2] = xin[(size_t)prow*DD + c2] + v;
                    } else if constexpr (MODE == 2) {
                        v += bias[c2];
                        v = (c2 < 4*dt) ? v : 0.f;
                        float gv = gelu_f(v);
                        __nv_bfloat16 h, l; bf16_split(gv, h, l);
                        g_hid_h[(size_t)row*RD + c2] = h;
                        g_hid_l[(size_t)row*RD + c2] = l;
                    } else {
                        v += bias[c2];
                        v = (c2 < dt) ? v : 0.f;
                        dout[(size_t)prow*DD + c2] = g_z[(size_t)row*DD + c2] + gate * v;
                    }
                }
            }
        }
    }
}

// ---------------- HMMA flash attention: head-level query skipping + key-prefix truncation ----------------
#define APITCH 72
__global__ __launch_bounds__(256)
void attn_kernel() {
    __shared__ uint16_t smH[128*APITCH];
    __shared__ uint16_t smL[128*APITCH];
    int bh = blockIdx.y;
    int b = bh >> 3;
    int h = bh & 7;
    int m0 = blockIdx.x * 128;         // rank within batch
    int tid = threadIdx.x;
    int lane = tid & 31, w = tid >> 5;
    int dtq = dt_of_rank(m0);          // query tile homogeneous

    if (h*64 >= dtq) {
        // whole head masked for these query rows: write zeros, done
        for (int i = tid; i < 128*64; i += 256) {
            int r = i >> 6, f = i & 63;
            size_t off = (size_t)(b*NN + m0 + r)*DD + h*64 + f;
            g_o_h[off] = __float2bfloat16(0.f);
            g_o_l[off] = __float2bfloat16(0.f);
        }
        return;
    }

    const uint32_t* qp = g_q_p + (size_t)bh * NN * 64;
    const uint32_t* kp = g_k_p + (size_t)bh * NN * 64;
    const uint32_t* vp = g_v_p + (size_t)bh * NN * 64;

    // keys beyond lim have exactly-zero K,V slices for this head (expert-sorted prefix)
    int lim = (h == 0) ? NN : (h == 1) ? 1024 : (h < 4) ? 512 : 256;

    // ---- fill Q tile ----
    {
        int row = tid >> 1, hb = (tid & 1) * 32;
        const uint4* src = (const uint4*)(qp + (size_t)(m0 + row)*64 + hb);
        #pragma unroll
        for (int j = 0; j < 8; j++) {
            uint4 u = src[j];
            uint32_t ws[4] = {u.x, u.y, u.z, u.w};
            #pragma unroll
            for (int q = 0; q < 4; q++) {
                int d = hb + j*4 + q;
                smH[row*APITCH + d] = (uint16_t)(ws[q] & 0xFFFFu);
                smL[row*APITCH + d] = (uint16_t)(ws[q] >> 16);
            }
        }
    }
    __syncthreads();
    uint32_t qa_h[4][4], qa_l[4][4];
    {
        uint32_t qoffH = smem_u32(smH) + ((w*16 + (lane & 15))*APITCH + (lane >> 4)*8)*2;
        uint32_t qoffL = smem_u32(smL) + ((w*16 + (lane & 15))*APITCH + (lane >> 4)*8)*2;
        #pragma unroll
        for (int kc = 0; kc < 4; kc++) {
            ldsm_x4(qa_h[kc], qoffH + kc*16*2);
            ldsm_x4(qa_l[kc], qoffL + kc*16*2);
        }
    }
    __syncthreads();

    uint32_t kbH = smem_u32(smH) + ((lane & 7)*APITCH + ((lane >> 3) & 1)*8)*2;
    uint32_t kbL = smem_u32(smL) + ((lane & 7)*APITCH + ((lane >> 3) & 1)*8)*2;
    uint32_t vbH = smem_u32(smH) + ((64 + (lane & 7))*APITCH + ((lane >> 3) & 1)*8)*2;
    uint32_t vbL = smem_u32(smL) + ((64 + (lane & 7))*APITCH + ((lane >> 3) & 1)*8)*2;

    float O[8][4] = {};
    float mold0 = -1e30f, mold1 = -1e30f, lsum0 = 0.f, lsum1 = 0.f;

    for (int n0 = 0; n0 < lim; n0 += 64) {
        {
            int key = tid >> 2, part = (tid & 3)*16;
            const uint4* src = (const uint4*)(kp + (size_t)(n0 + key)*64 + part);
            #pragma unroll
            for (int j = 0; j < 4; j++) {
                uint4 u = src[j];
                uint32_t ws[4] = {u.x, u.y, u.z, u.w};
                #pragma unroll
                for (int q = 0; q < 4; q++) {
                    int d = part + j*4 + q;
                    smH[key*APITCH + d] = (uint16_t)(ws[q] & 0xFFFFu);
                    smL[key*APITCH + d] = (uint16_t)(ws[q] >> 16);
                }
            }
        }
        {
            int key = tid & 63, dbase = (tid >> 6)*16;
            const uint4* src = (const uint4*)(vp + (size_t)(n0 + key)*64 + dbase);
            #pragma unroll
            for (int j = 0; j < 4; j++) {
                uint4 u = src[j];
                uint32_t ws[4] = {u.x, u.y, u.z, u.w};
                #pragma unroll
                for (int q = 0; q < 4; q++) {
                    int d = dbase + j*4 + q;
                    smH[(64 + d)*APITCH + key] = (uint16_t)(ws[q] & 0xFFFFu);
                    smL[(64 + d)*APITCH + key] = (uint16_t)(ws[q] >> 16);
                }
            }
        }
        __syncthreads();

        float S[8][4] = {};
        #pragma unroll
        for (int kc = 0; kc < 4; kc++) {
            #pragma unroll
            for (int nt = 0; nt < 8; nt++) {
                uint32_t kb2[2], kl2[2];
                ldsm_x2(kb2, kbH + (nt*8*APITCH + kc*16)*2);
                ldsm_x2(kl2, kbL + (nt*8*APITCH + kc*16)*2);
                mma16816(S[nt], qa_h[kc], kb2);
                mma16816(S[nt], qa_h[kc], kl2);
                mma16816(S[nt], qa_l[kc], kb2);
            }
        }
        float mx0 = -1e30f, mx1 = -1e30f;
        #pragma unroll
        for (int nt = 0; nt < 8; nt++) {
            S[nt][0] *= 0.125f; S[nt][1] *= 0.125f; S[nt][2] *= 0.125f; S[nt][3] *= 0.125f;
            mx0 = fmaxf(mx0, fmaxf(S[nt][0], S[nt][1]));
            mx1 = fmaxf(mx1, fmaxf(S[nt][2], S[nt][3]));
        }
        mx0 = fmaxf(mx0, __shfl_xor_sync(0xffffffffu, mx0, 1));
        mx0 = fmaxf(mx0, __shfl_xor_sync(0xffffffffu, mx0, 2));
        mx1 = fmaxf(mx1, __shfl_xor_sync(0xffffffffu, mx1, 1));
        mx1 = fmaxf(mx1, __shfl_xor_sync(0xffffffffu, mx1, 2));
        float mn0 = fmaxf(mold0, mx0), mn1 = fmaxf(mold1, mx1);
        float corr0 = fast_exp(mold0 - mn0), corr1 = fast_exp(mold1 - mn1);
        float rs0 = 0.f, rs1 = 0.f;
        #pragma unroll
        for (int nt = 0; nt < 8; nt++) {
            S[nt][0] = fast_exp(S[nt][0] - mn0); rs0 += S[nt][0];
            S[nt][1] = fast_exp(S[nt][1] - mn0); rs0 += S[nt][1];
            S[nt][2] = fast_exp(S[nt][2] - mn1); rs1 += S[nt][2];
            S[nt][3] = fast_exp(S[nt][3] - mn1); rs1 += S[nt][3];
        }
        rs0 += __shfl_xor_sync(0xffffffffu, rs0, 1);
        rs0 += __shfl_xor_sync(0xffffffffu, rs0, 2);
        rs1 += __shfl_xor_sync(0xffffffffu, rs1, 1);
        rs1 += __shfl_xor_sync(0xffffffffu, rs1, 2);
        lsum0 = lsum0*corr0 + rs0;
        lsum1 = lsum1*corr1 + rs1;
        #pragma unroll
        for (int nt = 0; nt < 8; nt++) {
            O[nt][0] *= corr0; O[nt][1] *= corr0; O[nt][2] *= corr1; O[nt][3] *= corr1;
        }
        mold0 = mn0; mold1 = mn1;

        #pragma unroll
        for (int kc = 0; kc < 4; kc++) {
            uint32_t pah[4], pal[4];
            #pragma unroll
            for (int half = 0; half < 2; half++) {
                int nt = 2*kc + half;
                __nv_bfloat16 h0,l0,h1,l1,h2,l2,h3,l3;
                bf16_split(S[nt][0], h0, l0);
                bf16_split(S[nt][1], h1, l1);
                bf16_split(S[nt][2], h2, l2);
                bf16_split(S[nt][3], h3, l3);
                pah[half*2+0] = (uint32_t)__bfloat16_as_ushort(h0) | ((uint32_t)__bfloat16_as_ushort(h1) << 16);
                pah[half*2+1] = (uint32_t)__bfloat16_as_ushort(h2) | ((uint32_t)__bfloat16_as_ushort(h3) << 16);
                pal[half*2+0] = (uint32_t)__bfloat16_as_ushort(l0) | ((uint32_t)__bfloat16_as_ushort(l1) << 16);
                pal[half*2+1] = (uint32_t)__bfloat16_as_ushort(l2) | ((uint32_t)__bfloat16_as_ushort(l3) << 16);
            }
            #pragma unroll
            for (int nt = 0; nt < 8; nt++) {
                uint32_t vh2[2], vl2[2];
                ldsm_x2(vh2, vbH + (nt*8*APITCH + kc*16)*2);
                ldsm_x2(vl2, vbL + (nt*8*APITCH + kc*16)*2);
                mma16816(O[nt], pah, vh2);
                mma16816(O[nt], pah, vl2);
                mma16816(O[nt], pal, vh2);
            }
        }
        __syncthreads();
    }

    // ---- virtual tile for the (NN - lim) exactly-zero keys: score = 0, V = 0 ----
    if (lim < NN) {
        float nz = (float)(NN - lim);
        float mn0 = fmaxf(mold0, 0.f), mn1 = fmaxf(mold1, 0.f);
        float corr0 = fast_exp(mold0 - mn0), corr1 = fast_exp(mold1 - mn1);
        lsum0 = lsum0*corr0 + nz*fast_exp(0.f - mn0);
        lsum1 = lsum1*corr1 + nz*fast_exp(0.f - mn1);
        #pragma unroll
        for (int nt = 0; nt < 8; nt++) {
            O[nt][0] *= corr0; O[nt][1] *= corr0; O[nt][2] *= corr1; O[nt][3] *= corr1;
        }
    }

    float inv0 = 1.f / lsum0, inv1 = 1.f / lsum1;
    int r0 = m0 + w*16 + (lane >> 2);
    int row0 = b*NN + r0, row1 = row0 + 8;
    #pragma unroll
    for (int nt = 0; nt < 8; nt++) {
        #pragma unroll
        for (int e = 0; e < 2; e++) {
            int feat = h*64 + nt*8 + (lane & 3)*2 + e;
            float v0 = O[nt][e]*inv0;       // head fully active (feat < dtq guaranteed)
            float v1 = O[nt][2+e]*inv1;
            __nv_bfloat16 hh, ll;
            bf16_split(v0, hh, ll);
            g_o_h[(size_t)row0*DD + feat] = hh;
            g_o_l[(size_t)row0*DD + feat] = ll;
            bf16_split(v1, hh, ll);
            g_o_h[(size_t)row1*DD + feat] = hh;
            g_o_l[(size_t)row1*DD + feat] = ll;
        }
    }
}

// extra outputs (assigned, rp) — token space, reference returns the full tuple
__global__ void extras_kernel(float* dout, int out_size) {
    int i = blockIdx.x * blockDim.x + threadIdx.x;
    if (i >= MROWS) return;
    const int base = MROWS*DD;
    if (out_size >= base + MROWS)   dout[base + i] = (float)g_assigned[i];
    if (out_size >= base + 2*MROWS) dout[base + MROWS + i] = g_rp[i];
}

extern "C" void kernel_launch(void* const* d_in, const int* in_sizes, int n_in,
                              void* d_out, int out_size) {
    const float* x    = (const float*)d_in[0];
    const float* r_w  = (const float*)d_in[1];
    const float* r_b  = (const float*)d_in[2];
    const float* g1   = (const float*)d_in[3];
    const float* b1   = (const float*)d_in[4];
    const float* g2   = (const float*)d_in[5];
    const float* b2   = (const float*)d_in[6];
    const float* wqkv = (const float*)d_in[7];
    const float* wo   = (const float*)d_in[8];
    const float* bo   = (const float*)d_in[9];
    const float* w1   = (const float*)d_in[10];
    const float* b1f  = (const float*)d_in[11];
    const float* w2   = (const float*)d_in[12];
    const float* b2f  = (const float*)d_in[13];
    const float* alpha= (const float*)d_in[14];
    float* out = (float*)d_out;

    constexpr int TG_SMEM = 4 * 128 * PITCH * 2;  // 40960 B

    router_kernel<<<MROWS/4, 128>>>(x, r_w, r_b);
    assign_kernel<<<BB, 1024>>>();
    wconv_kernel<0><<<dim3(1536/32, 512/32),  dim3(32,8)>>>(wqkv);
    wconv_kernel<1><<<dim3(512/32,  512/32),  dim3(32,8)>>>(wo);
    wconv_kernel<2><<<dim3(2048/32, 512/32),  dim3(32,8)>>>(w1);
    wconv_kernel<3><<<dim3(512/32,  2048/32), dim3(32,8)>>>(w2);
    ln_mask_kernel<0><<<MROWS, 128>>>(x, g1, b1);
    tgemm_kernel<0><<<dim3(1536/128, MROWS/128), 256, TG_SMEM>>>(nullptr, nullptr, nullptr, nullptr);
    attn_kernel<<<dim3(NN/128, BB*HH), 256>>>();
    tgemm_kernel<1><<<dim3(512/128, MROWS/128), 256, TG_SMEM>>>(bo, x, nullptr, nullptr);
    ln_mask_kernel<1><<<MROWS, 128>>>(nullptr, g2, b2);
    tgemm_kernel<2><<<dim3(2048/128, MROWS/128), 256, TG_SMEM>>>(b1f, nullptr, nullptr, nullptr);
    tgemm_kernel<3><<<dim3(512/128, MROWS/128), 256, TG_SMEM>>>(b2f, nullptr, alpha, out);
    if (out_size > MROWS*DD)
        extras_kernel<<<(MROWS+255)/256, 256>>>(out, out_size);
}